// round 13
// baseline (speedup 1.0000x reference)
#include <cuda_runtime.h>
#include <cuda_fp16.h>
#include <cstdint>

// ---------------------------------------------------------------------------
// Problem constants (shapes fixed by the dataset)
// ---------------------------------------------------------------------------
#define NMAX 50000
#define EMAX 800000
#define H1 4
#define C1 64
#define F1 (H1 * C1)   // 256
#define C2 64
#define SCAN_BLK 1024
#define NBMAX 64

// ---------------------------------------------------------------------------
// Scratch (static device memory; no allocation anywhere)
// ---------------------------------------------------------------------------
__device__ __half g_h1[(size_t)NMAX * F1];     // layer1 features, fp16 (gather-only)
__device__ float  g_as1[NMAX * H1];
__device__ float  g_ad1[NMAX * H1];
__device__ float  g_agg1[(size_t)NMAX * F1];   // layer1 output (fp32, feeds GEMM2)
__device__ __half g_h2[(size_t)NMAX * C2];     // layer2 features, fp16 (gather-only)
__device__ float  g_as2[NMAX];
__device__ float  g_ad2[NMAX];
__device__ float  g_w4[(size_t)EMAX * H1];     // layer1 per-edge softmax weights (CSR order)
__device__ float  g_w1[EMAX];                  // layer2 per-edge softmax weights
__device__ int g_deg[NMAX];
__device__ int g_rowptr[NMAX + 1];
__device__ int g_cursor[NMAX];
__device__ int g_csrc[EMAX];
__device__ int g_bsum[NBMAX];
__device__ int g_bofs[NBMAX];

__device__ __forceinline__ float lrelu(float v) { return v > 0.f ? v : 0.2f * v; }

struct half4 { __half2 a, b; };

// ---------------------------------------------------------------------------
// GEMM with fused attention-scalar epilogue. C stored as fp16.
// 64x64 tile, TK=32, 256 threads, 4x4 micro-tile. FFMA roofline.
// ---------------------------------------------------------------------------
__global__ __launch_bounds__(256) void gemm_att_kernel(
    const float* __restrict__ A, const float* __restrict__ B,
    __half* __restrict__ C, const float* __restrict__ att_s,
    const float* __restrict__ att_d, float* __restrict__ as_out,
    float* __restrict__ ad_out, int M, int N, int K)
{
    const int TM = 64, TK = 32;
    __shared__ float As[32][64 + 4];
    __shared__ float Bs[32][64];

    int bm = blockIdx.y * TM;
    int bn = blockIdx.x * 64;
    int tid = threadIdx.x;
    int tx = tid & 15;
    int ty = tid >> 4;

    float acc[4][4] = {};

    for (int k0 = 0; k0 < K; k0 += TK) {
        #pragma unroll
        for (int i = 0; i < 2; ++i) {
            int idx = tid + i * 256;
            int r  = idx >> 3;
            int c4 = idx & 7;
            int gr = bm + r;
            float4 v = make_float4(0.f, 0.f, 0.f, 0.f);
            if (gr < M) v = *(const float4*)&A[(size_t)gr * K + k0 + c4 * 4];
            As[c4 * 4 + 0][r] = v.x;
            As[c4 * 4 + 1][r] = v.y;
            As[c4 * 4 + 2][r] = v.z;
            As[c4 * 4 + 3][r] = v.w;
        }
        #pragma unroll
        for (int i = 0; i < 2; ++i) {
            int idx = tid + i * 256;
            int r  = idx >> 4;
            int c4 = idx & 15;
            float4 v = *(const float4*)&B[(size_t)(k0 + r) * N + bn + c4 * 4];
            *(float4*)&Bs[r][c4 * 4] = v;
        }
        __syncthreads();

        #pragma unroll
        for (int k = 0; k < TK; ++k) {
            float a[4], b[4];
            #pragma unroll
            for (int i = 0; i < 4; ++i) a[i] = As[k][ty * 4 + i];
            #pragma unroll
            for (int j = 0; j < 4; ++j) b[j] = Bs[k][tx * 4 + j];
            #pragma unroll
            for (int i = 0; i < 4; ++i)
                #pragma unroll
                for (int j = 0; j < 4; ++j) acc[i][j] += a[i] * b[j];
        }
        __syncthreads();
    }

    #pragma unroll
    for (int i = 0; i < 4; ++i) {
        int gr = bm + ty * 4 + i;
        if (gr < M) {
            half4 hv;
            hv.a = __floats2half2_rn(acc[i][0], acc[i][1]);
            hv.b = __floats2half2_rn(acc[i][2], acc[i][3]);
            *(half4*)&C[(size_t)gr * N + bn + tx * 4] = hv;
        }
    }

    int hh = blockIdx.x;
    int Hh = N >> 6;
    float4 avs = *(const float4*)&att_s[hh * 64 + tx * 4];
    float4 avd = *(const float4*)&att_d[hh * 64 + tx * 4];
    #pragma unroll
    for (int i = 0; i < 4; ++i) {
        float sa = acc[i][0] * avs.x + acc[i][1] * avs.y + acc[i][2] * avs.z + acc[i][3] * avs.w;
        float sd = acc[i][0] * avd.x + acc[i][1] * avd.y + acc[i][2] * avd.z + acc[i][3] * avd.w;
        #pragma unroll
        for (int o = 8; o; o >>= 1) {
            sa += __shfl_down_sync(0xffffffffu, sa, o, 16);
            sd += __shfl_down_sync(0xffffffffu, sd, o, 16);
        }
        int gr = bm + ty * 4 + i;
        if (tx == 0 && gr < M) {
            as_out[gr * Hh + hh] = sa;
            ad_out[gr * Hh + hh] = sd;
        }
    }
}

// ---------------------------------------------------------------------------
// CSR build: histogram, 3-phase parallel scan, scatter.
// ---------------------------------------------------------------------------
__global__ __launch_bounds__(256) void hist_kernel(
    const int* __restrict__ ei, int* __restrict__ deg, int E)
{
    int t = blockIdx.x * blockDim.x + threadIdx.x;
    if (t < E) atomicAdd(&deg[ei[E + t]], 1);
}

__global__ __launch_bounds__(256) void block_sum_kernel(
    const int* __restrict__ deg, int* __restrict__ bsum, int Nn)
{
    __shared__ int ss[256];
    int tid = threadIdx.x;
    int base = blockIdx.x * SCAN_BLK + tid * 4;
    int s = 0;
    #pragma unroll
    for (int i = 0; i < 4; ++i) {
        int idx = base + i;
        if (idx < Nn) s += deg[idx];
    }
    ss[tid] = s;
    __syncthreads();
    #pragma unroll
    for (int o = 128; o; o >>= 1) {
        if (tid < o) ss[tid] += ss[tid + o];
        __syncthreads();
    }
    if (tid == 0) bsum[blockIdx.x] = ss[0];
}

__global__ __launch_bounds__(64) void scan_bsums_kernel(
    const int* __restrict__ bsum, int* __restrict__ bofs,
    int* __restrict__ rowptr, int Nn, int NB)
{
    __shared__ int ss[64];
    int tid = threadIdx.x;
    int v = (tid < NB) ? bsum[tid] : 0;
    ss[tid] = v;
    __syncthreads();
    #pragma unroll
    for (int o = 1; o < 64; o <<= 1) {
        int u = (tid >= o) ? ss[tid - o] : 0;
        __syncthreads();
        ss[tid] += u;
        __syncthreads();
    }
    if (tid < NB) bofs[tid] = ss[tid] - v;
    if (tid == NB - 1) rowptr[Nn] = ss[tid];
}

__global__ __launch_bounds__(256) void write_rowptr_kernel(
    const int* __restrict__ deg, const int* __restrict__ bofs,
    int* __restrict__ rowptr, int* __restrict__ cursor, int Nn)
{
    __shared__ int ss[256];
    int tid = threadIdx.x;
    int base = blockIdx.x * SCAN_BLK + tid * 4;
    int loc[4];
    int tsum = 0;
    #pragma unroll
    for (int i = 0; i < 4; ++i) {
        int idx = base + i;
        loc[i] = (idx < Nn) ? deg[idx] : 0;
        tsum += loc[i];
    }
    ss[tid] = tsum;
    __syncthreads();
    #pragma unroll
    for (int o = 1; o < 256; o <<= 1) {
        int u = (tid >= o) ? ss[tid - o] : 0;
        __syncthreads();
        ss[tid] += u;
        __syncthreads();
    }
    int run = (tid ? ss[tid - 1] : 0) + bofs[blockIdx.x];
    #pragma unroll
    for (int i = 0; i < 4; ++i) {
        int idx = base + i;
        if (idx < Nn) {
            rowptr[idx] = run;
            cursor[idx] = run;
            run += loc[i];
        }
    }
}

__global__ __launch_bounds__(256) void scatter_kernel(
    const int* __restrict__ ei, int* __restrict__ cursor,
    int* __restrict__ csrc, int E)
{
    int t = blockIdx.x * blockDim.x + threadIdx.x;
    if (t < E) {
        int d = ei[E + t];
        int p = atomicAdd(&cursor[d], 1);
        csrc[p] = ei[t];
    }
}

// ---------------------------------------------------------------------------
// Per-edge softmax weights (lane-parallel over edges; latency hidden).
// ---------------------------------------------------------------------------
__global__ __launch_bounds__(256) void edge_w4_kernel(
    const int* __restrict__ rowptr, const int* __restrict__ csrc,
    const float* __restrict__ as_, const float* __restrict__ ad_,
    float* __restrict__ w4, int Nn)
{
    int dst  = (blockIdx.x * blockDim.x + threadIdx.x) >> 5;
    int lane = threadIdx.x & 31;
    if (dst >= Nn) return;
    int beg = rowptr[dst], end = rowptr[dst + 1];
    float4 ad4 = *(const float4*)&ad_[dst * 4];
    for (int j = beg + lane; j < end; j += 32) {
        int s = csrc[j];
        float4 a = *(const float4*)&as_[s * 4];
        float4 w;
        w.x = __expf(lrelu(a.x + ad4.x));
        w.y = __expf(lrelu(a.y + ad4.y));
        w.z = __expf(lrelu(a.z + ad4.z));
        w.w = __expf(lrelu(a.w + ad4.w));
        *(float4*)&w4[(size_t)j * 4] = w;
    }
}

__global__ __launch_bounds__(256) void edge_w1_kernel(
    const int* __restrict__ rowptr, const int* __restrict__ csrc,
    const float* __restrict__ as_, const float* __restrict__ ad_,
    float* __restrict__ w1, int Nn)
{
    int dst  = (blockIdx.x * blockDim.x + threadIdx.x) >> 5;
    int lane = threadIdx.x & 31;
    if (dst >= Nn) return;
    int beg = rowptr[dst], end = rowptr[dst + 1];
    float ad = ad_[dst];
    for (int j = beg + lane; j < end; j += 32) {
        int s = csrc[j];
        w1[j] = __expf(lrelu(as_[s] + ad));
    }
}

// ---------------------------------------------------------------------------
// Fused GAT gather, layer1 (H=4, C=64). Warp per (dst, head-pair).
// The TWO 16-lane halves of the warp process DISJOINT halves of the edge
// list (lanes cover all 128 channels of the head pair via uint4 = 8 halves),
// then combine partials with shfl_xor(16). Serial chain ~deg/2. Bias+ELU.
// ---------------------------------------------------------------------------
__global__ __launch_bounds__(256) void gat_gather_h4(
    const int* __restrict__ rowptr, const int* __restrict__ csrc,
    const float* __restrict__ w4,
    const float* __restrict__ as_, const float* __restrict__ ad_,
    const __half* __restrict__ hfeat, const float* __restrict__ bias,
    float* __restrict__ outp, int Nn)
{
    int gid  = blockIdx.x * 8 + (threadIdx.x >> 5);
    int lane = threadIdx.x & 31;
    int dst  = gid >> 1;
    int sub  = gid & 1;
    if (dst >= Nn) return;

    int beg = rowptr[dst], end = rowptr[dst + 1];
    int len = end - beg;
    int mid = beg + (len >> 1);
    int half = lane >> 4;         // 0 or 1
    int l    = lane & 15;         // channel group: 8 halves each
    // channels sub*128 + l*8 .. +7 ; l<8 -> first head of pair, l>=8 -> second
    bool headB = (l >= 8);

    float acc[8] = {};
    float den0 = 0.f, den1 = 0.f;

    // self-loop handled by half 0 only
    if (half == 0) {
        float2 ad2 = *(const float2*)&ad_[dst * 4 + sub * 2];
        float2 as2 = *(const float2*)&as_[dst * 4 + sub * 2];
        float ex0 = __expf(lrelu(as2.x + ad2.x));
        float ex1 = __expf(lrelu(as2.y + ad2.y));
        den0 += ex0; den1 += ex1;
        const uint4* hp = (const uint4*)(hfeat + (size_t)dst * F1 + sub * 128);
        uint4 raw = hp[l];
        float ex = headB ? ex1 : ex0;
        float2 a0 = __half22float2(*(__half2*)&raw.x);
        float2 a1 = __half22float2(*(__half2*)&raw.y);
        float2 a2 = __half22float2(*(__half2*)&raw.z);
        float2 a3 = __half22float2(*(__half2*)&raw.w);
        acc[0] += ex * a0.x; acc[1] += ex * a0.y;
        acc[2] += ex * a1.x; acc[3] += ex * a1.y;
        acc[4] += ex * a2.x; acc[5] += ex * a2.y;
        acc[6] += ex * a3.x; acc[7] += ex * a3.y;
    }

    int jb = half ? mid : beg;
    int je = half ? end : mid;
    #pragma unroll 4
    for (int j = jb; j < je; ++j) {
        int s = csrc[j];
        float2 w2 = *(const float2*)&w4[(size_t)j * 4 + sub * 2];
        den0 += w2.x; den1 += w2.y;
        const uint4* hp = (const uint4*)(hfeat + (size_t)s * F1 + sub * 128);
        uint4 raw = hp[l];
        float ex = headB ? w2.y : w2.x;
        float2 a0 = __half22float2(*(__half2*)&raw.x);
        float2 a1 = __half22float2(*(__half2*)&raw.y);
        float2 a2 = __half22float2(*(__half2*)&raw.z);
        float2 a3 = __half22float2(*(__half2*)&raw.w);
        acc[0] += ex * a0.x; acc[1] += ex * a0.y;
        acc[2] += ex * a1.x; acc[3] += ex * a1.y;
        acc[4] += ex * a2.x; acc[5] += ex * a2.y;
        acc[6] += ex * a3.x; acc[7] += ex * a3.y;
    }

    // combine the two halves (lane l gets lane l+16's partials)
    #pragma unroll
    for (int i = 0; i < 8; ++i)
        acc[i] += __shfl_xor_sync(0xffffffffu, acc[i], 16);
    den0 += __shfl_xor_sync(0xffffffffu, den0, 16);
    den1 += __shfl_xor_sync(0xffffffffu, den1, 16);

    if (half == 0) {
        float r = 1.f / (headB ? den1 : den0);
        const float* bp = &bias[sub * 128 + l * 8];
        float o[8];
        #pragma unroll
        for (int i = 0; i < 8; ++i) {
            float v = acc[i] * r + bp[i];
            o[i] = v > 0.f ? v : expm1f(v);
        }
        float* op = &outp[(size_t)dst * F1 + sub * 128 + l * 8];
        *(float4*)&op[0] = make_float4(o[0], o[1], o[2], o[3]);
        *(float4*)&op[4] = make_float4(o[4], o[5], o[6], o[7]);
    }
}

// ---------------------------------------------------------------------------
// Fused GAT gather, layer2 (H=1, C=64). Warp per dst; the two 16-lane halves
// process disjoint edge halves (uint2 = 4 halves per lane covers 64 ch),
// combined with shfl_xor(16). Bias fused. Output fp32 (d_out).
// ---------------------------------------------------------------------------
__global__ __launch_bounds__(256) void gat_gather_h1(
    const int* __restrict__ rowptr, const int* __restrict__ csrc,
    const float* __restrict__ w1,
    const float* __restrict__ as_, const float* __restrict__ ad_,
    const __half* __restrict__ hfeat, const float* __restrict__ bias,
    float* __restrict__ outp, int Nn)
{
    int dst  = blockIdx.x * 8 + (threadIdx.x >> 5);
    int lane = threadIdx.x & 31;
    if (dst >= Nn) return;

    int beg = rowptr[dst], end = rowptr[dst + 1];
    int len = end - beg;
    int mid = beg + (len >> 1);
    int half = lane >> 4;
    int l    = lane & 15;

    float4 acc = make_float4(0.f, 0.f, 0.f, 0.f);
    float den = 0.f;

    if (half == 0) {
        float ex = __expf(lrelu(as_[dst] + ad_[dst]));
        den += ex;
        const uint2* hp = (const uint2*)(hfeat + (size_t)dst * C2);
        uint2 raw = hp[l];
        float2 f0 = __half22float2(*(__half2*)&raw.x);
        float2 f1 = __half22float2(*(__half2*)&raw.y);
        acc.x += ex * f0.x; acc.y += ex * f0.y; acc.z += ex * f1.x; acc.w += ex * f1.y;
    }

    int jb = half ? mid : beg;
    int je = half ? end : mid;
    #pragma unroll 4
    for (int j = jb; j < je; ++j) {
        int s = csrc[j];
        float ex = w1[j];
        den += ex;
        const uint2* hp = (const uint2*)(hfeat + (size_t)s * C2);
        uint2 raw = hp[l];
        float2 f0 = __half22float2(*(__half2*)&raw.x);
        float2 f1 = __half22float2(*(__half2*)&raw.y);
        acc.x += ex * f0.x; acc.y += ex * f0.y; acc.z += ex * f1.x; acc.w += ex * f1.y;
    }

    acc.x += __shfl_xor_sync(0xffffffffu, acc.x, 16);
    acc.y += __shfl_xor_sync(0xffffffffu, acc.y, 16);
    acc.z += __shfl_xor_sync(0xffffffffu, acc.z, 16);
    acc.w += __shfl_xor_sync(0xffffffffu, acc.w, 16);
    den   += __shfl_xor_sync(0xffffffffu, den, 16);

    if (half == 0) {
        float r = 1.f / den;
        float4 b = *(const float4*)&bias[l * 4];
        float4 o = make_float4(acc.x * r + b.x, acc.y * r + b.y,
                               acc.z * r + b.z, acc.w * r + b.w);
        *(float4*)&outp[(size_t)dst * C2 + l * 4] = o;
    }
}

// ---------------------------------------------------------------------------
// Launch: CSR build on a side stream, overlapped with the layer1 GEMM.
// ---------------------------------------------------------------------------
extern "C" void kernel_launch(void* const* d_in, const int* in_sizes, int n_in,
                              void* d_out, int out_size)
{
    const float* x    = (const float*)d_in[0];
    const int*   ei   = (const int*)  d_in[1];
    const float* W1   = (const float*)d_in[2];
    const float* aS1  = (const float*)d_in[3];
    const float* aD1  = (const float*)d_in[4];
    const float* b1   = (const float*)d_in[5];
    const float* W2   = (const float*)d_in[6];
    const float* aS2  = (const float*)d_in[7];
    const float* aD2  = (const float*)d_in[8];
    const float* b2   = (const float*)d_in[9];
    float* out = (float*)d_out;

    const int N = in_sizes[0] / 128;   // 50000
    const int E = in_sizes[1] / 2;     // 800000
    const int NB = (N + SCAN_BLK - 1) / SCAN_BLK;

    __half *h1, *h2;
    float *as1, *ad1, *agg1, *as2, *ad2, *w4, *w1;
    int *deg, *rowptr, *cursor, *csrc, *bsum, *bofs;
    cudaGetSymbolAddress((void**)&h1,     g_h1);
    cudaGetSymbolAddress((void**)&as1,    g_as1);
    cudaGetSymbolAddress((void**)&ad1,    g_ad1);
    cudaGetSymbolAddress((void**)&agg1,   g_agg1);
    cudaGetSymbolAddress((void**)&h2,     g_h2);
    cudaGetSymbolAddress((void**)&as2,    g_as2);
    cudaGetSymbolAddress((void**)&ad2,    g_ad2);
    cudaGetSymbolAddress((void**)&w4,     g_w4);
    cudaGetSymbolAddress((void**)&w1,     g_w1);
    cudaGetSymbolAddress((void**)&deg,    g_deg);
    cudaGetSymbolAddress((void**)&rowptr, g_rowptr);
    cudaGetSymbolAddress((void**)&cursor, g_cursor);
    cudaGetSymbolAddress((void**)&csrc,   g_csrc);
    cudaGetSymbolAddress((void**)&bsum,   g_bsum);
    cudaGetSymbolAddress((void**)&bofs,   g_bofs);

    static cudaStream_t side = nullptr;
    static cudaEvent_t evf = nullptr, evj = nullptr;
    if (side == nullptr) {
        cudaStreamCreateWithFlags(&side, cudaStreamNonBlocking);
        cudaEventCreateWithFlags(&evf, cudaEventDisableTiming);
        cudaEventCreateWithFlags(&evj, cudaEventDisableTiming);
    }

    const int warpBlocks = (N + 7) / 8;

    // -------- fork: CSR build on side stream --------
    cudaEventRecord(evf, 0);
    cudaStreamWaitEvent(side, evf, 0);
    cudaMemsetAsync(deg, 0, (size_t)N * sizeof(int), side);
    hist_kernel<<<(E + 255) / 256, 256, 0, side>>>(ei, deg, E);
    block_sum_kernel<<<NB, 256, 0, side>>>(deg, bsum, N);
    scan_bsums_kernel<<<1, 64, 0, side>>>(bsum, bofs, rowptr, N, NB);
    write_rowptr_kernel<<<NB, 256, 0, side>>>(deg, bofs, rowptr, cursor, N);
    scatter_kernel<<<(E + 255) / 256, 256, 0, side>>>(ei, cursor, csrc, E);
    cudaEventRecord(evj, side);

    // -------- main stream: layer1 GEMM (independent of CSR) --------
    {
        dim3 grid(F1 / 64, (N + 63) / 64);
        gemm_att_kernel<<<grid, 256>>>(x, W1, h1, aS1, aD1, as1, ad1, N, F1, 128);
    }

    // -------- join, then the dependent pipeline --------
    cudaStreamWaitEvent(0, evj, 0);
    edge_w4_kernel<<<warpBlocks, 256>>>(rowptr, csrc, as1, ad1, w4, N);
    gat_gather_h4<<<(2 * N + 7) / 8, 256>>>(rowptr, csrc, w4, as1, ad1, h1, b1, agg1, N);
    {
        dim3 grid(C2 / 64, (N + 63) / 64);
        gemm_att_kernel<<<grid, 256>>>(agg1, W2, h2, aS2, aD2, as2, ad2, N, C2, F1);
    }
    edge_w1_kernel<<<warpBlocks, 256>>>(rowptr, csrc, as2, ad2, w1, N);
    gat_gather_h1<<<warpBlocks, 256>>>(rowptr, csrc, w1, as2, ad2, h2, b2, out, N);
}

// round 14
// speedup vs baseline: 1.2395x; 1.2395x over previous
#include <cuda_runtime.h>
#include <cuda_fp16.h>
#include <cstdint>

// ---------------------------------------------------------------------------
// Problem constants (shapes fixed by the dataset)
// ---------------------------------------------------------------------------
#define NMAX 50000
#define EMAX 800000
#define H1 4
#define C1 64
#define F1 (H1 * C1)   // 256
#define C2 64
#define SCAN_BLK 1024
#define NBMAX 64

// ---------------------------------------------------------------------------
// Scratch (static device memory; no allocation anywhere)
// ---------------------------------------------------------------------------
__device__ __half g_xh[(size_t)NMAX * 128];    // x converted to fp16
__device__ __half g_w1h[128 * F1];             // W1 converted to fp16
__device__ __half g_h1[(size_t)NMAX * F1];     // layer1 features, fp16 (gather-only)
__device__ float  g_as1[NMAX * H1];
__device__ float  g_ad1[NMAX * H1];
__device__ float  g_agg1[(size_t)NMAX * F1];   // layer1 output (fp32, feeds GEMM2)
__device__ __half g_h2[(size_t)NMAX * C2];     // layer2 features, fp16 (gather-only)
__device__ float  g_as2[NMAX];
__device__ float  g_ad2[NMAX];
__device__ float  g_w4[(size_t)EMAX * H1];     // layer1 per-edge softmax weights
__device__ float  g_w1[EMAX];                  // layer2 per-edge softmax weights
__device__ int g_deg[NMAX];
__device__ int g_rowptr[NMAX + 1];
__device__ int g_cursor[NMAX];
__device__ int g_csrc[EMAX];
__device__ int g_bsum[NBMAX];
__device__ int g_bofs[NBMAX];

__device__ __forceinline__ float lrelu(float v) { return v > 0.f ? v : 0.2f * v; }

struct half4 { __half2 a, b; };

// ---------------------------------------------------------------------------
// fp32 -> fp16 elementwise conversion (vectorized), n must be multiple of 4
// ---------------------------------------------------------------------------
__global__ __launch_bounds__(256) void f2h_kernel(
    const float* __restrict__ in, __half* __restrict__ out, long n4)
{
    long t = (long)blockIdx.x * blockDim.x + threadIdx.x;
    if (t >= n4) return;
    float4 v = ((const float4*)in)[t];
    half4 h;
    h.a = __floats2half2_rn(v.x, v.y);
    h.b = __floats2half2_rn(v.z, v.w);
    ((half4*)out)[t] = h;
}

// ---------------------------------------------------------------------------
// fp16 tensor-core GEMM (mma.sync.m16n8k16) with fused attention epilogue.
// C[M,N] = A[M,K]*B[K,N], A/B fp16 row-major, C fp16, att scalars fp32.
// Block 128x64, BK=32, 256 thr = 8 warps (4 M x 2 N), warp tile 32x32.
// Requires K%32==0, N%64==0. M guarded. Each 64-wide N tile = one head.
// ---------------------------------------------------------------------------
__global__ __launch_bounds__(256) void hgemm_att_kernel(
    const __half* __restrict__ A, const __half* __restrict__ B,
    __half* __restrict__ C, const float* __restrict__ att_s,
    const float* __restrict__ att_d, float* __restrict__ as_out,
    float* __restrict__ ad_out, int M, int N, int K)
{
    const int BM = 128, BK = 32, SAS = 40;  // smem stride in halves (pad 8)
    __shared__ __half As[BM][SAS];          // [m][k]
    __shared__ __half Bs[64][SAS];          // transposed: [n][k]
    __shared__ float red[BM][4];            // att partials [row][wn*2 + {s,d}]

    int tid = threadIdx.x;
    int wid = tid >> 5, lane = tid & 31;
    int wm = (wid & 3) * 32;                // warp M offset
    int wn = (wid >> 2) * 32;               // warp N offset
    int g  = lane >> 2;                     // 0..7
    int tg = lane & 3;                      // 0..3
    int bm = blockIdx.y * BM;
    int bn = blockIdx.x * 64;

    float acc[2][4][4] = {};

    for (int k0 = 0; k0 < K; k0 += BK) {
        // ---- A tile 128x32 halves: 512 uint4, 2 per thread ----
        #pragma unroll
        for (int i = 0; i < 2; ++i) {
            int idx = tid + i * 256;
            int r  = idx >> 2;
            int c8 = idx & 3;
            int gr = bm + r;
            uint4 v = make_uint4(0u, 0u, 0u, 0u);
            if (gr < M) v = *(const uint4*)&A[(size_t)gr * K + k0 + c8 * 8];
            *(uint4*)&As[r][c8 * 8] = v;
        }
        // ---- B tile 32x64 halves, stored TRANSPOSED into Bs[n][k] ----
        {
            int kr = tid >> 3;              // 0..31
            int cb = tid & 7;               // 0..7
            uint4 v = *(const uint4*)&B[(size_t)(k0 + kr) * N + bn + cb * 8];
            __half h[8];
            *(uint4*)h = v;
            #pragma unroll
            for (int j = 0; j < 8; ++j) Bs[cb * 8 + j][kr] = h[j];
        }
        __syncthreads();

        #pragma unroll
        for (int ks = 0; ks < 2; ++ks) {
            int kb = ks * 16;
            unsigned a[2][4], b[4][2];
            #pragma unroll
            for (int mm = 0; mm < 2; ++mm) {
                int r0 = wm + mm * 16 + g;
                a[mm][0] = *(const unsigned*)&As[r0][kb + tg * 2];
                a[mm][1] = *(const unsigned*)&As[r0 + 8][kb + tg * 2];
                a[mm][2] = *(const unsigned*)&As[r0][kb + tg * 2 + 8];
                a[mm][3] = *(const unsigned*)&As[r0 + 8][kb + tg * 2 + 8];
            }
            #pragma unroll
            for (int nn = 0; nn < 4; ++nn) {
                int c0 = wn + nn * 8 + g;
                b[nn][0] = *(const unsigned*)&Bs[c0][kb + tg * 2];
                b[nn][1] = *(const unsigned*)&Bs[c0][kb + tg * 2 + 8];
            }
            #pragma unroll
            for (int mm = 0; mm < 2; ++mm)
                #pragma unroll
                for (int nn = 0; nn < 4; ++nn) {
                    asm("mma.sync.aligned.m16n8k16.row.col.f32.f16.f16.f32 "
                        "{%0,%1,%2,%3},{%4,%5,%6,%7},{%8,%9},{%0,%1,%2,%3};"
                        : "+f"(acc[mm][nn][0]), "+f"(acc[mm][nn][1]),
                          "+f"(acc[mm][nn][2]), "+f"(acc[mm][nn][3])
                        : "r"(a[mm][0]), "r"(a[mm][1]), "r"(a[mm][2]), "r"(a[mm][3]),
                          "r"(b[nn][0]), "r"(b[nn][1]));
                }
        }
        __syncthreads();
    }

    // ---- store C (fp16) ----
    #pragma unroll
    for (int mm = 0; mm < 2; ++mm) {
        int r0 = bm + wm + mm * 16 + g;
        #pragma unroll
        for (int nn = 0; nn < 4; ++nn) {
            int c = bn + wn + nn * 8 + tg * 2;
            if (r0 < M)
                *(__half2*)&C[(size_t)r0 * N + c] =
                    __floats2half2_rn(acc[mm][nn][0], acc[mm][nn][1]);
            if (r0 + 8 < M)
                *(__half2*)&C[(size_t)(r0 + 8) * N + c] =
                    __floats2half2_rn(acc[mm][nn][2], acc[mm][nn][3]);
        }
    }

    // ---- fused attention-scalar epilogue ----
    int hh = blockIdx.x;
    int Hh = N >> 6;
    float2 avs[4], avd[4];
    #pragma unroll
    for (int nn = 0; nn < 4; ++nn) {
        int c = hh * 64 + wn + nn * 8 + tg * 2;
        avs[nn] = *(const float2*)&att_s[c];
        avd[nn] = *(const float2*)&att_d[c];
    }
    #pragma unroll
    for (int mm = 0; mm < 2; ++mm) {
        #pragma unroll
        for (int h = 0; h < 2; ++h) {     // row half: g or g+8
            float sa = 0.f, sd = 0.f;
            #pragma unroll
            for (int nn = 0; nn < 4; ++nn) {
                sa += acc[mm][nn][2 * h] * avs[nn].x + acc[mm][nn][2 * h + 1] * avs[nn].y;
                sd += acc[mm][nn][2 * h] * avd[nn].x + acc[mm][nn][2 * h + 1] * avd[nn].y;
            }
            // reduce over the 4 tg lanes (same row)
            #pragma unroll
            for (int o = 1; o < 4; o <<= 1) {
                sa += __shfl_xor_sync(0xffffffffu, sa, o);
                sd += __shfl_xor_sync(0xffffffffu, sd, o);
            }
            if (tg == 0) {
                int lr = wm + mm * 16 + h * 8 + g;
                red[lr][(wn >> 5) * 2 + 0] = sa;
                red[lr][(wn >> 5) * 2 + 1] = sd;
            }
        }
    }
    __syncthreads();
    if (tid < BM) {
        int gr = bm + tid;
        if (gr < M) {
            as_out[gr * Hh + hh] = red[tid][0] + red[tid][2];
            ad_out[gr * Hh + hh] = red[tid][1] + red[tid][3];
        }
    }
}

// ---------------------------------------------------------------------------
// fp32 GEMM with fused attention epilogue (kept for layer 2). C fp16.
// ---------------------------------------------------------------------------
__global__ __launch_bounds__(256) void gemm_att_kernel(
    const float* __restrict__ A, const float* __restrict__ B,
    __half* __restrict__ C, const float* __restrict__ att_s,
    const float* __restrict__ att_d, float* __restrict__ as_out,
    float* __restrict__ ad_out, int M, int N, int K)
{
    const int TM = 64, TK = 32;
    __shared__ float As[32][64 + 4];
    __shared__ float Bs[32][64];

    int bm = blockIdx.y * TM;
    int bn = blockIdx.x * 64;
    int tid = threadIdx.x;
    int tx = tid & 15;
    int ty = tid >> 4;

    float acc[4][4] = {};

    for (int k0 = 0; k0 < K; k0 += TK) {
        #pragma unroll
        for (int i = 0; i < 2; ++i) {
            int idx = tid + i * 256;
            int r  = idx >> 3;
            int c4 = idx & 7;
            int gr = bm + r;
            float4 v = make_float4(0.f, 0.f, 0.f, 0.f);
            if (gr < M) v = *(const float4*)&A[(size_t)gr * K + k0 + c4 * 4];
            As[c4 * 4 + 0][r] = v.x;
            As[c4 * 4 + 1][r] = v.y;
            As[c4 * 4 + 2][r] = v.z;
            As[c4 * 4 + 3][r] = v.w;
        }
        #pragma unroll
        for (int i = 0; i < 2; ++i) {
            int idx = tid + i * 256;
            int r  = idx >> 4;
            int c4 = idx & 15;
            float4 v = *(const float4*)&B[(size_t)(k0 + r) * N + bn + c4 * 4];
            *(float4*)&Bs[r][c4 * 4] = v;
        }
        __syncthreads();

        #pragma unroll
        for (int k = 0; k < TK; ++k) {
            float a[4], b[4];
            #pragma unroll
            for (int i = 0; i < 4; ++i) a[i] = As[k][ty * 4 + i];
            #pragma unroll
            for (int j = 0; j < 4; ++j) b[j] = Bs[k][tx * 4 + j];
            #pragma unroll
            for (int i = 0; i < 4; ++i)
                #pragma unroll
                for (int j = 0; j < 4; ++j) acc[i][j] += a[i] * b[j];
        }
        __syncthreads();
    }

    #pragma unroll
    for (int i = 0; i < 4; ++i) {
        int gr = bm + ty * 4 + i;
        if (gr < M) {
            half4 hv;
            hv.a = __floats2half2_rn(acc[i][0], acc[i][1]);
            hv.b = __floats2half2_rn(acc[i][2], acc[i][3]);
            *(half4*)&C[(size_t)gr * N + bn + tx * 4] = hv;
        }
    }

    int hh = blockIdx.x;
    int Hh = N >> 6;
    float4 avs = *(const float4*)&att_s[hh * 64 + tx * 4];
    float4 avd = *(const float4*)&att_d[hh * 64 + tx * 4];
    #pragma unroll
    for (int i = 0; i < 4; ++i) {
        float sa = acc[i][0] * avs.x + acc[i][1] * avs.y + acc[i][2] * avs.z + acc[i][3] * avs.w;
        float sd = acc[i][0] * avd.x + acc[i][1] * avd.y + acc[i][2] * avd.z + acc[i][3] * avd.w;
        #pragma unroll
        for (int o = 8; o; o >>= 1) {
            sa += __shfl_down_sync(0xffffffffu, sa, o, 16);
            sd += __shfl_down_sync(0xffffffffu, sd, o, 16);
        }
        int gr = bm + ty * 4 + i;
        if (tx == 0 && gr < M) {
            as_out[gr * Hh + hh] = sa;
            ad_out[gr * Hh + hh] = sd;
        }
    }
}

// ---------------------------------------------------------------------------
// CSR build: histogram, 3-phase parallel scan, scatter.
// ---------------------------------------------------------------------------
__global__ __launch_bounds__(256) void hist_kernel(
    const int* __restrict__ ei, int* __restrict__ deg, int E)
{
    int t = blockIdx.x * blockDim.x + threadIdx.x;
    if (t < E) atomicAdd(&deg[ei[E + t]], 1);
}

__global__ __launch_bounds__(256) void block_sum_kernel(
    const int* __restrict__ deg, int* __restrict__ bsum, int Nn)
{
    __shared__ int ss[256];
    int tid = threadIdx.x;
    int base = blockIdx.x * SCAN_BLK + tid * 4;
    int s = 0;
    #pragma unroll
    for (int i = 0; i < 4; ++i) {
        int idx = base + i;
        if (idx < Nn) s += deg[idx];
    }
    ss[tid] = s;
    __syncthreads();
    #pragma unroll
    for (int o = 128; o; o >>= 1) {
        if (tid < o) ss[tid] += ss[tid + o];
        __syncthreads();
    }
    if (tid == 0) bsum[blockIdx.x] = ss[0];
}

__global__ __launch_bounds__(64) void scan_bsums_kernel(
    const int* __restrict__ bsum, int* __restrict__ bofs,
    int* __restrict__ rowptr, int Nn, int NB)
{
    __shared__ int ss[64];
    int tid = threadIdx.x;
    int v = (tid < NB) ? bsum[tid] : 0;
    ss[tid] = v;
    __syncthreads();
    #pragma unroll
    for (int o = 1; o < 64; o <<= 1) {
        int u = (tid >= o) ? ss[tid - o] : 0;
        __syncthreads();
        ss[tid] += u;
        __syncthreads();
    }
    if (tid < NB) bofs[tid] = ss[tid] - v;
    if (tid == NB - 1) rowptr[Nn] = ss[tid];
}

__global__ __launch_bounds__(256) void write_rowptr_kernel(
    const int* __restrict__ deg, const int* __restrict__ bofs,
    int* __restrict__ rowptr, int* __restrict__ cursor, int Nn)
{
    __shared__ int ss[256];
    int tid = threadIdx.x;
    int base = blockIdx.x * SCAN_BLK + tid * 4;
    int loc[4];
    int tsum = 0;
    #pragma unroll
    for (int i = 0; i < 4; ++i) {
        int idx = base + i;
        loc[i] = (idx < Nn) ? deg[idx] : 0;
        tsum += loc[i];
    }
    ss[tid] = tsum;
    __syncthreads();
    #pragma unroll
    for (int o = 1; o < 256; o <<= 1) {
        int u = (tid >= o) ? ss[tid - o] : 0;
        __syncthreads();
        ss[tid] += u;
        __syncthreads();
    }
    int run = (tid ? ss[tid - 1] : 0) + bofs[blockIdx.x];
    #pragma unroll
    for (int i = 0; i < 4; ++i) {
        int idx = base + i;
        if (idx < Nn) {
            rowptr[idx] = run;
            cursor[idx] = run;
            run += loc[i];
        }
    }
}

__global__ __launch_bounds__(256) void scatter_kernel(
    const int* __restrict__ ei, int* __restrict__ cursor,
    int* __restrict__ csrc, int E)
{
    int t = blockIdx.x * blockDim.x + threadIdx.x;
    if (t < E) {
        int d = ei[E + t];
        int p = atomicAdd(&cursor[d], 1);
        csrc[p] = ei[t];
    }
}

// ---------------------------------------------------------------------------
// Per-edge softmax weights (lane-parallel over edges; latency hidden).
// ---------------------------------------------------------------------------
__global__ __launch_bounds__(256) void edge_w4_kernel(
    const int* __restrict__ rowptr, const int* __restrict__ csrc,
    const float* __restrict__ as_, const float* __restrict__ ad_,
    float* __restrict__ w4, int Nn)
{
    int dst  = (blockIdx.x * blockDim.x + threadIdx.x) >> 5;
    int lane = threadIdx.x & 31;
    if (dst >= Nn) return;
    int beg = rowptr[dst], end = rowptr[dst + 1];
    float4 ad4 = *(const float4*)&ad_[dst * 4];
    for (int j = beg + lane; j < end; j += 32) {
        int s = csrc[j];
        float4 a = *(const float4*)&as_[s * 4];
        float4 w;
        w.x = __expf(lrelu(a.x + ad4.x));
        w.y = __expf(lrelu(a.y + ad4.y));
        w.z = __expf(lrelu(a.z + ad4.z));
        w.w = __expf(lrelu(a.w + ad4.w));
        *(float4*)&w4[(size_t)j * 4] = w;
    }
}

__global__ __launch_bounds__(256) void edge_w1_kernel(
    const int* __restrict__ rowptr, const int* __restrict__ csrc,
    const float* __restrict__ as_, const float* __restrict__ ad_,
    float* __restrict__ w1, int Nn)
{
    int dst  = (blockIdx.x * blockDim.x + threadIdx.x) >> 5;
    int lane = threadIdx.x & 31;
    if (dst >= Nn) return;
    int beg = rowptr[dst], end = rowptr[dst + 1];
    float ad = ad_[dst];
    for (int j = beg + lane; j < end; j += 32) {
        int s = csrc[j];
        w1[j] = __expf(lrelu(as_[s] + ad));
    }
}

// ---------------------------------------------------------------------------
// Fused GAT gather, layer1 (H=4, C=64). TWO warps per dst (head pairs),
// fp16 features (uint2 per lane), precomputed weights, unroll 8. Bias+ELU.
// (R11 configuration — best measured.)
// ---------------------------------------------------------------------------
__global__ __launch_bounds__(256) void gat_gather_h4(
    const int* __restrict__ rowptr, const int* __restrict__ csrc,
    const float* __restrict__ w4,
    const float* __restrict__ as_, const float* __restrict__ ad_,
    const __half* __restrict__ hfeat, const float* __restrict__ bias,
    float* __restrict__ outp, int Nn)
{
    int gid  = blockIdx.x * 8 + (threadIdx.x >> 5);
    int lane = threadIdx.x & 31;
    int dst  = gid >> 1;
    int sub  = gid & 1;
    if (dst >= Nn) return;

    int beg = rowptr[dst], end = rowptr[dst + 1];
    bool hi = (lane & 16) != 0;
    float4 acc = make_float4(0.f, 0.f, 0.f, 0.f);
    float den0 = 0.f, den1 = 0.f;

    // self-loop
    {
        float2 ad2 = *(const float2*)&ad_[dst * 4 + sub * 2];
        float2 as2 = *(const float2*)&as_[dst * 4 + sub * 2];
        float ex0 = __expf(lrelu(as2.x + ad2.x));
        float ex1 = __expf(lrelu(as2.y + ad2.y));
        den0 += ex0; den1 += ex1;
        const uint2* hp = (const uint2*)(hfeat + (size_t)dst * F1);
        uint2 raw = hp[sub * 32 + lane];
        float2 f0 = __half22float2(*(__half2*)&raw.x);
        float2 f1 = __half22float2(*(__half2*)&raw.y);
        float ex = hi ? ex1 : ex0;
        acc.x += ex * f0.x; acc.y += ex * f0.y; acc.z += ex * f1.x; acc.w += ex * f1.y;
    }
    #pragma unroll 8
    for (int j = beg; j < end; ++j) {
        int s = csrc[j];
        float2 w2 = *(const float2*)&w4[(size_t)j * 4 + sub * 2];
        den0 += w2.x; den1 += w2.y;
        const uint2* hp = (const uint2*)(hfeat + (size_t)s * F1);
        uint2 raw = hp[sub * 32 + lane];
        float2 f0 = __half22float2(*(__half2*)&raw.x);
        float2 f1 = __half22float2(*(__half2*)&raw.y);
        float ex = hi ? w2.y : w2.x;
        acc.x += ex * f0.x; acc.y += ex * f0.y; acc.z += ex * f1.x; acc.w += ex * f1.y;
    }

    float r = 1.f / (hi ? den1 : den0);
    float4 b = *(const float4*)&bias[sub * 128 + lane * 4];
    float4 o;
    o.x = acc.x * r + b.x; o.y = acc.y * r + b.y;
    o.z = acc.z * r + b.z; o.w = acc.w * r + b.w;
    o.x = o.x > 0.f ? o.x : expm1f(o.x);
    o.y = o.y > 0.f ? o.y : expm1f(o.y);
    o.z = o.z > 0.f ? o.z : expm1f(o.z);
    o.w = o.w > 0.f ? o.w : expm1f(o.w);
    *(float4*)&outp[(size_t)dst * F1 + sub * 128 + lane * 4] = o;
}

// ---------------------------------------------------------------------------
// Fused GAT gather, layer2 (H=1, C=64). Half-warp per dst (R11 config).
// ---------------------------------------------------------------------------
__global__ __launch_bounds__(256) void gat_gather_h1(
    const int* __restrict__ rowptr, const int* __restrict__ csrc,
    const float* __restrict__ w1,
    const float* __restrict__ as_, const float* __restrict__ ad_,
    const __half* __restrict__ hfeat, const float* __restrict__ bias,
    float* __restrict__ outp, int Nn)
{
    int dst = blockIdx.x * 16 + (threadIdx.x >> 4);
    int l   = threadIdx.x & 15;
    if (dst >= Nn) return;

    int beg = rowptr[dst], end = rowptr[dst + 1];
    float4 acc = make_float4(0.f, 0.f, 0.f, 0.f);
    float den = 0.f;
    {
        float ex = __expf(lrelu(as_[dst] + ad_[dst]));
        den += ex;
        const uint2* hp = (const uint2*)(hfeat + (size_t)dst * C2);
        uint2 raw = hp[l];
        float2 f0 = __half22float2(*(__half2*)&raw.x);
        float2 f1 = __half22float2(*(__half2*)&raw.y);
        acc.x += ex * f0.x; acc.y += ex * f0.y; acc.z += ex * f1.x; acc.w += ex * f1.y;
    }
    #pragma unroll 8
    for (int j = beg; j < end; ++j) {
        int s = csrc[j];
        float ex = w1[j];
        den += ex;
        const uint2* hp = (const uint2*)(hfeat + (size_t)s * C2);
        uint2 raw = hp[l];
        float2 f0 = __half22float2(*(__half2*)&raw.x);
        float2 f1 = __half22float2(*(__half2*)&raw.y);
        acc.x += ex * f0.x; acc.y += ex * f0.y; acc.z += ex * f1.x; acc.w += ex * f1.y;
    }
    float r = 1.f / den;
    float4 b = *(const float4*)&bias[l * 4];
    float4 o = make_float4(acc.x * r + b.x, acc.y * r + b.y,
                           acc.z * r + b.z, acc.w * r + b.w);
    *(float4*)&outp[(size_t)dst * C2 + l * 4] = o;
}

// ---------------------------------------------------------------------------
// Launch: CSR build on a side stream, overlapped with convert + layer1 GEMM.
// ---------------------------------------------------------------------------
extern "C" void kernel_launch(void* const* d_in, const int* in_sizes, int n_in,
                              void* d_out, int out_size)
{
    const float* x    = (const float*)d_in[0];
    const int*   ei   = (const int*)  d_in[1];
    const float* W1   = (const float*)d_in[2];
    const float* aS1  = (const float*)d_in[3];
    const float* aD1  = (const float*)d_in[4];
    const float* b1   = (const float*)d_in[5];
    const float* W2   = (const float*)d_in[6];
    const float* aS2  = (const float*)d_in[7];
    const float* aD2  = (const float*)d_in[8];
    const float* b2   = (const float*)d_in[9];
    float* out = (float*)d_out;

    const int N = in_sizes[0] / 128;   // 50000
    const int E = in_sizes[1] / 2;     // 800000
    const int NB = (N + SCAN_BLK - 1) / SCAN_BLK;

    __half *xh, *w1h, *h1, *h2;
    float *as1, *ad1, *agg1, *as2, *ad2, *w4, *w1;
    int *deg, *rowptr, *cursor, *csrc, *bsum, *bofs;
    cudaGetSymbolAddress((void**)&xh,     g_xh);
    cudaGetSymbolAddress((void**)&w1h,    g_w1h);
    cudaGetSymbolAddress((void**)&h1,     g_h1);
    cudaGetSymbolAddress((void**)&as1,    g_as1);
    cudaGetSymbolAddress((void**)&ad1,    g_ad1);
    cudaGetSymbolAddress((void**)&agg1,   g_agg1);
    cudaGetSymbolAddress((void**)&h2,     g_h2);
    cudaGetSymbolAddress((void**)&as2,    g_as2);
    cudaGetSymbolAddress((void**)&ad2,    g_ad2);
    cudaGetSymbolAddress((void**)&w4,     g_w4);
    cudaGetSymbolAddress((void**)&w1,     g_w1);
    cudaGetSymbolAddress((void**)&deg,    g_deg);
    cudaGetSymbolAddress((void**)&rowptr, g_rowptr);
    cudaGetSymbolAddress((void**)&cursor, g_cursor);
    cudaGetSymbolAddress((void**)&csrc,   g_csrc);
    cudaGetSymbolAddress((void**)&bsum,   g_bsum);
    cudaGetSymbolAddress((void**)&bofs,   g_bofs);

    static cudaStream_t side = nullptr;
    static cudaEvent_t evf = nullptr, evj = nullptr;
    if (side == nullptr) {
        cudaStreamCreateWithFlags(&side, cudaStreamNonBlocking);
        cudaEventCreateWithFlags(&evf, cudaEventDisableTiming);
        cudaEventCreateWithFlags(&evj, cudaEventDisableTiming);
    }

    const int warpBlocks = (N + 7) / 8;

    // -------- fork: CSR build on side stream --------
    cudaEventRecord(evf, 0);
    cudaStreamWaitEvent(side, evf, 0);
    cudaMemsetAsync(deg, 0, (size_t)N * sizeof(int), side);
    hist_kernel<<<(E + 255) / 256, 256, 0, side>>>(ei, deg, E);
    block_sum_kernel<<<NB, 256, 0, side>>>(deg, bsum, N);
    scan_bsums_kernel<<<1, 64, 0, side>>>(bsum, bofs, rowptr, N, NB);
    write_rowptr_kernel<<<NB, 256, 0, side>>>(deg, bofs, rowptr, cursor, N);
    scatter_kernel<<<(E + 255) / 256, 256, 0, side>>>(ei, cursor, csrc, E);
    cudaEventRecord(evj, side);

    // -------- main stream: convert inputs to fp16, then tensor GEMM1 --------
    {
        long n4 = (long)N * 128 / 4;
        f2h_kernel<<<(int)((n4 + 255) / 256), 256>>>(x, xh, n4);
        long w4n = 128 * F1 / 4;
        f2h_kernel<<<(int)((w4n + 255) / 256), 256>>>(W1, w1h, w4n);
    }
    {
        dim3 grid(F1 / 64, (N + 127) / 128);
        hgemm_att_kernel<<<grid, 256>>>(xh, w1h, h1, aS1, aD1, as1, ad1, N, F1, 128);
    }

    // -------- join, then the dependent pipeline --------
    cudaStreamWaitEvent(0, evj, 0);
    edge_w4_kernel<<<warpBlocks, 256>>>(rowptr, csrc, as1, ad1, w4, N);
    gat_gather_h4<<<(2 * N + 7) / 8, 256>>>(rowptr, csrc, w4, as1, ad1, h1, b1, agg1, N);
    {
        dim3 grid(C2 / 64, (N + 63) / 64);
        gemm_att_kernel<<<grid, 256>>>(agg1, W2, h2, aS2, aD2, as2, ad2, N, C2, F1);
    }
    edge_w1_kernel<<<warpBlocks, 256>>>(rowptr, csrc, as2, ad2, w1, N);
    gat_gather_h1<<<(N + 15) / 16, 256>>>(rowptr, csrc, w1, as2, ad2, h2, b2, out, N);
}

// round 15
// speedup vs baseline: 1.4988x; 1.2092x over previous
#include <cuda_runtime.h>
#include <cuda_fp16.h>
#include <cstdint>

// ---------------------------------------------------------------------------
// Problem constants (shapes fixed by the dataset)
// ---------------------------------------------------------------------------
#define NMAX 50000
#define EMAX 800000
#define H1 4
#define C1 64
#define F1 (H1 * C1)   // 256
#define C2 64
#define SCAN_BLK 1024
#define NBMAX 64

// ---------------------------------------------------------------------------
// Scratch (static device memory; no allocation anywhere)
// ---------------------------------------------------------------------------
__device__ __half g_xh[(size_t)NMAX * 128];    // x fp16
__device__ __half g_w1h[128 * F1];             // W1 fp16
__device__ __half g_w2h[F1 * C2];              // W2 fp16
__device__ __half g_h1[(size_t)NMAX * F1];     // layer1 features fp16
__device__ float  g_as1[NMAX * H1];
__device__ float  g_ad1[NMAX * H1];
__device__ __half g_agg1h[(size_t)NMAX * F1];  // layer1 output fp16 (feeds hgemm2)
__device__ __half g_h2[(size_t)NMAX * C2];     // layer2 features fp16
__device__ float  g_as2[NMAX];
__device__ float  g_ad2[NMAX];
__device__ float  g_w4[(size_t)EMAX * H1];     // layer1 per-edge softmax weights
__device__ float  g_w1[EMAX];                  // layer2 per-edge softmax weights
__device__ int g_deg[NMAX];
__device__ int g_rowptr[NMAX + 1];
__device__ int g_cursor[NMAX];
__device__ int g_csrc[EMAX];
__device__ int g_bsum[NBMAX];
__device__ int g_bofs[NBMAX];

__device__ __forceinline__ float lrelu(float v) { return v > 0.f ? v : 0.2f * v; }

struct half4 { __half2 a, b; };

// ---------------------------------------------------------------------------
// fp32 -> fp16 elementwise conversion (vectorized), n multiple of 4
// ---------------------------------------------------------------------------
__global__ __launch_bounds__(256) void f2h_kernel(
    const float* __restrict__ in, __half* __restrict__ out, long n4)
{
    long t = (long)blockIdx.x * blockDim.x + threadIdx.x;
    if (t >= n4) return;
    float4 v = ((const float4*)in)[t];
    half4 h;
    h.a = __floats2half2_rn(v.x, v.y);
    h.b = __floats2half2_rn(v.z, v.w);
    ((half4*)out)[t] = h;
}

// ---------------------------------------------------------------------------
// fp16 tensor-core GEMM (mma.sync.m16n8k16) with fused attention epilogue.
// C[M,N] = A[M,K]*B[K,N], A/B fp16 row-major, C fp16, att scalars fp32.
// Block 128x64, BK=32, 256 thr = 8 warps (4 M x 2 N), warp tile 32x32.
// Requires K%32==0, N%64==0. M guarded. Each 64-wide N tile = one head.
// ---------------------------------------------------------------------------
__global__ __launch_bounds__(256) void hgemm_att_kernel(
    const __half* __restrict__ A, const __half* __restrict__ B,
    __half* __restrict__ C, const float* __restrict__ att_s,
    const float* __restrict__ att_d, float* __restrict__ as_out,
    float* __restrict__ ad_out, int M, int N, int K)
{
    const int BM = 128, BK = 32, SAS = 40;  // smem stride in halves (pad 8)
    __shared__ __half As[BM][SAS];          // [m][k]
    __shared__ __half Bs[64][SAS];          // transposed: [n][k]
    __shared__ float red[BM][4];            // att partials

    int tid = threadIdx.x;
    int wid = tid >> 5, lane = tid & 31;
    int wm = (wid & 3) * 32;
    int wn = (wid >> 2) * 32;
    int g  = lane >> 2;
    int tg = lane & 3;
    int bm = blockIdx.y * BM;
    int bn = blockIdx.x * 64;

    float acc[2][4][4] = {};

    for (int k0 = 0; k0 < K; k0 += BK) {
        #pragma unroll
        for (int i = 0; i < 2; ++i) {
            int idx = tid + i * 256;
            int r  = idx >> 2;
            int c8 = idx & 3;
            int gr = bm + r;
            uint4 v = make_uint4(0u, 0u, 0u, 0u);
            if (gr < M) v = *(const uint4*)&A[(size_t)gr * K + k0 + c8 * 8];
            *(uint4*)&As[r][c8 * 8] = v;
        }
        {
            int kr = tid >> 3;
            int cb = tid & 7;
            uint4 v = *(const uint4*)&B[(size_t)(k0 + kr) * N + bn + cb * 8];
            __half h[8];
            *(uint4*)h = v;
            #pragma unroll
            for (int j = 0; j < 8; ++j) Bs[cb * 8 + j][kr] = h[j];
        }
        __syncthreads();

        #pragma unroll
        for (int ks = 0; ks < 2; ++ks) {
            int kb = ks * 16;
            unsigned a[2][4], b[4][2];
            #pragma unroll
            for (int mm = 0; mm < 2; ++mm) {
                int r0 = wm + mm * 16 + g;
                a[mm][0] = *(const unsigned*)&As[r0][kb + tg * 2];
                a[mm][1] = *(const unsigned*)&As[r0 + 8][kb + tg * 2];
                a[mm][2] = *(const unsigned*)&As[r0][kb + tg * 2 + 8];
                a[mm][3] = *(const unsigned*)&As[r0 + 8][kb + tg * 2 + 8];
            }
            #pragma unroll
            for (int nn = 0; nn < 4; ++nn) {
                int c0 = wn + nn * 8 + g;
                b[nn][0] = *(const unsigned*)&Bs[c0][kb + tg * 2];
                b[nn][1] = *(const unsigned*)&Bs[c0][kb + tg * 2 + 8];
            }
            #pragma unroll
            for (int mm = 0; mm < 2; ++mm)
                #pragma unroll
                for (int nn = 0; nn < 4; ++nn) {
                    asm("mma.sync.aligned.m16n8k16.row.col.f32.f16.f16.f32 "
                        "{%0,%1,%2,%3},{%4,%5,%6,%7},{%8,%9},{%0,%1,%2,%3};"
                        : "+f"(acc[mm][nn][0]), "+f"(acc[mm][nn][1]),
                          "+f"(acc[mm][nn][2]), "+f"(acc[mm][nn][3])
                        : "r"(a[mm][0]), "r"(a[mm][1]), "r"(a[mm][2]), "r"(a[mm][3]),
                          "r"(b[nn][0]), "r"(b[nn][1]));
                }
        }
        __syncthreads();
    }

    // store C (fp16)
    #pragma unroll
    for (int mm = 0; mm < 2; ++mm) {
        int r0 = bm + wm + mm * 16 + g;
        #pragma unroll
        for (int nn = 0; nn < 4; ++nn) {
            int c = bn + wn + nn * 8 + tg * 2;
            if (r0 < M)
                *(__half2*)&C[(size_t)r0 * N + c] =
                    __floats2half2_rn(acc[mm][nn][0], acc[mm][nn][1]);
            if (r0 + 8 < M)
                *(__half2*)&C[(size_t)(r0 + 8) * N + c] =
                    __floats2half2_rn(acc[mm][nn][2], acc[mm][nn][3]);
        }
    }

    // fused attention-scalar epilogue (fp32 accumulators)
    int hh = blockIdx.x;
    int Hh = N >> 6;
    float2 avs[4], avd[4];
    #pragma unroll
    for (int nn = 0; nn < 4; ++nn) {
        int c = hh * 64 + wn + nn * 8 + tg * 2;
        avs[nn] = *(const float2*)&att_s[c];
        avd[nn] = *(const float2*)&att_d[c];
    }
    #pragma unroll
    for (int mm = 0; mm < 2; ++mm) {
        #pragma unroll
        for (int h = 0; h < 2; ++h) {
            float sa = 0.f, sd = 0.f;
            #pragma unroll
            for (int nn = 0; nn < 4; ++nn) {
                sa += acc[mm][nn][2 * h] * avs[nn].x + acc[mm][nn][2 * h + 1] * avs[nn].y;
                sd += acc[mm][nn][2 * h] * avd[nn].x + acc[mm][nn][2 * h + 1] * avd[nn].y;
            }
            #pragma unroll
            for (int o = 1; o < 4; o <<= 1) {
                sa += __shfl_xor_sync(0xffffffffu, sa, o);
                sd += __shfl_xor_sync(0xffffffffu, sd, o);
            }
            if (tg == 0) {
                int lr = wm + mm * 16 + h * 8 + g;
                red[lr][(wn >> 5) * 2 + 0] = sa;
                red[lr][(wn >> 5) * 2 + 1] = sd;
            }
        }
    }
    __syncthreads();
    if (tid < BM) {
        int gr = bm + tid;
        if (gr < M) {
            as_out[gr * Hh + hh] = red[tid][0] + red[tid][2];
            ad_out[gr * Hh + hh] = red[tid][1] + red[tid][3];
        }
    }
}

// ---------------------------------------------------------------------------
// CSR build: histogram, 3-phase parallel scan, scatter.
// ---------------------------------------------------------------------------
__global__ __launch_bounds__(256) void hist_kernel(
    const int* __restrict__ ei, int* __restrict__ deg, int E)
{
    int t = blockIdx.x * blockDim.x + threadIdx.x;
    if (t < E) atomicAdd(&deg[ei[E + t]], 1);
}

__global__ __launch_bounds__(256) void block_sum_kernel(
    const int* __restrict__ deg, int* __restrict__ bsum, int Nn)
{
    __shared__ int ss[256];
    int tid = threadIdx.x;
    int base = blockIdx.x * SCAN_BLK + tid * 4;
    int s = 0;
    #pragma unroll
    for (int i = 0; i < 4; ++i) {
        int idx = base + i;
        if (idx < Nn) s += deg[idx];
    }
    ss[tid] = s;
    __syncthreads();
    #pragma unroll
    for (int o = 128; o; o >>= 1) {
        if (tid < o) ss[tid] += ss[tid + o];
        __syncthreads();
    }
    if (tid == 0) bsum[blockIdx.x] = ss[0];
}

__global__ __launch_bounds__(64) void scan_bsums_kernel(
    const int* __restrict__ bsum, int* __restrict__ bofs,
    int* __restrict__ rowptr, int Nn, int NB)
{
    __shared__ int ss[64];
    int tid = threadIdx.x;
    int v = (tid < NB) ? bsum[tid] : 0;
    ss[tid] = v;
    __syncthreads();
    #pragma unroll
    for (int o = 1; o < 64; o <<= 1) {
        int u = (tid >= o) ? ss[tid - o] : 0;
        __syncthreads();
        ss[tid] += u;
        __syncthreads();
    }
    if (tid < NB) bofs[tid] = ss[tid] - v;
    if (tid == NB - 1) rowptr[Nn] = ss[tid];
}

__global__ __launch_bounds__(256) void write_rowptr_kernel(
    const int* __restrict__ deg, const int* __restrict__ bofs,
    int* __restrict__ rowptr, int* __restrict__ cursor, int Nn)
{
    __shared__ int ss[256];
    int tid = threadIdx.x;
    int base = blockIdx.x * SCAN_BLK + tid * 4;
    int loc[4];
    int tsum = 0;
    #pragma unroll
    for (int i = 0; i < 4; ++i) {
        int idx = base + i;
        loc[i] = (idx < Nn) ? deg[idx] : 0;
        tsum += loc[i];
    }
    ss[tid] = tsum;
    __syncthreads();
    #pragma unroll
    for (int o = 1; o < 256; o <<= 1) {
        int u = (tid >= o) ? ss[tid - o] : 0;
        __syncthreads();
        ss[tid] += u;
        __syncthreads();
    }
    int run = (tid ? ss[tid - 1] : 0) + bofs[blockIdx.x];
    #pragma unroll
    for (int i = 0; i < 4; ++i) {
        int idx = base + i;
        if (idx < Nn) {
            rowptr[idx] = run;
            cursor[idx] = run;
            run += loc[i];
        }
    }
}

__global__ __launch_bounds__(256) void scatter_kernel(
    const int* __restrict__ ei, int* __restrict__ cursor,
    int* __restrict__ csrc, int E)
{
    int t = blockIdx.x * blockDim.x + threadIdx.x;
    if (t < E) {
        int d = ei[E + t];
        int p = atomicAdd(&cursor[d], 1);
        csrc[p] = ei[t];
    }
}

// ---------------------------------------------------------------------------
// Per-edge softmax weights (lane-parallel over edges; latency hidden).
// ---------------------------------------------------------------------------
__global__ __launch_bounds__(256) void edge_w4_kernel(
    const int* __restrict__ rowptr, const int* __restrict__ csrc,
    const float* __restrict__ as_, const float* __restrict__ ad_,
    float* __restrict__ w4, int Nn)
{
    int dst  = (blockIdx.x * blockDim.x + threadIdx.x) >> 5;
    int lane = threadIdx.x & 31;
    if (dst >= Nn) return;
    int beg = rowptr[dst], end = rowptr[dst + 1];
    float4 ad4 = *(const float4*)&ad_[dst * 4];
    for (int j = beg + lane; j < end; j += 32) {
        int s = csrc[j];
        float4 a = *(const float4*)&as_[s * 4];
        float4 w;
        w.x = __expf(lrelu(a.x + ad4.x));
        w.y = __expf(lrelu(a.y + ad4.y));
        w.z = __expf(lrelu(a.z + ad4.z));
        w.w = __expf(lrelu(a.w + ad4.w));
        *(float4*)&w4[(size_t)j * 4] = w;
    }
}

__global__ __launch_bounds__(256) void edge_w1_kernel(
    const int* __restrict__ rowptr, const int* __restrict__ csrc,
    const float* __restrict__ as_, const float* __restrict__ ad_,
    float* __restrict__ w1, int Nn)
{
    int dst  = (blockIdx.x * blockDim.x + threadIdx.x) >> 5;
    int lane = threadIdx.x & 31;
    if (dst >= Nn) return;
    int beg = rowptr[dst], end = rowptr[dst + 1];
    float ad = ad_[dst];
    for (int j = beg + lane; j < end; j += 32) {
        int s = csrc[j];
        w1[j] = __expf(lrelu(as_[s] + ad));
    }
}

// ---------------------------------------------------------------------------
// Fused GAT gather, layer1 (H=4, C=64). TWO warps per dst (head pairs),
// fp16 features, precomputed weights, unroll 8. Bias+ELU fused.
// OUTPUT fp16 (feeds the fp16 tensor GEMM2 directly).
// ---------------------------------------------------------------------------
__global__ __launch_bounds__(256) void gat_gather_h4(
    const int* __restrict__ rowptr, const int* __restrict__ csrc,
    const float* __restrict__ w4,
    const float* __restrict__ as_, const float* __restrict__ ad_,
    const __half* __restrict__ hfeat, const float* __restrict__ bias,
    __half* __restrict__ outp, int Nn)
{
    int gid  = blockIdx.x * 8 + (threadIdx.x >> 5);
    int lane = threadIdx.x & 31;
    int dst  = gid >> 1;
    int sub  = gid & 1;
    if (dst >= Nn) return;

    int beg = rowptr[dst], end = rowptr[dst + 1];
    bool hi = (lane & 16) != 0;
    float4 acc = make_float4(0.f, 0.f, 0.f, 0.f);
    float den0 = 0.f, den1 = 0.f;

    // self-loop
    {
        float2 ad2 = *(const float2*)&ad_[dst * 4 + sub * 2];
        float2 as2 = *(const float2*)&as_[dst * 4 + sub * 2];
        float ex0 = __expf(lrelu(as2.x + ad2.x));
        float ex1 = __expf(lrelu(as2.y + ad2.y));
        den0 += ex0; den1 += ex1;
        const uint2* hp = (const uint2*)(hfeat + (size_t)dst * F1);
        uint2 raw = hp[sub * 32 + lane];
        float2 f0 = __half22float2(*(__half2*)&raw.x);
        float2 f1 = __half22float2(*(__half2*)&raw.y);
        float ex = hi ? ex1 : ex0;
        acc.x += ex * f0.x; acc.y += ex * f0.y; acc.z += ex * f1.x; acc.w += ex * f1.y;
    }
    #pragma unroll 8
    for (int j = beg; j < end; ++j) {
        int s = csrc[j];
        float2 w2 = *(const float2*)&w4[(size_t)j * 4 + sub * 2];
        den0 += w2.x; den1 += w2.y;
        const uint2* hp = (const uint2*)(hfeat + (size_t)s * F1);
        uint2 raw = hp[sub * 32 + lane];
        float2 f0 = __half22float2(*(__half2*)&raw.x);
        float2 f1 = __half22float2(*(__half2*)&raw.y);
        float ex = hi ? w2.y : w2.x;
        acc.x += ex * f0.x; acc.y += ex * f0.y; acc.z += ex * f1.x; acc.w += ex * f1.y;
    }

    float r = 1.f / (hi ? den1 : den0);
    float4 b = *(const float4*)&bias[sub * 128 + lane * 4];
    float4 o;
    o.x = acc.x * r + b.x; o.y = acc.y * r + b.y;
    o.z = acc.z * r + b.z; o.w = acc.w * r + b.w;
    o.x = o.x > 0.f ? o.x : expm1f(o.x);
    o.y = o.y > 0.f ? o.y : expm1f(o.y);
    o.z = o.z > 0.f ? o.z : expm1f(o.z);
    o.w = o.w > 0.f ? o.w : expm1f(o.w);
    half4 hv;
    hv.a = __floats2half2_rn(o.x, o.y);
    hv.b = __floats2half2_rn(o.z, o.w);
    *(half4*)&outp[(size_t)dst * F1 + sub * 128 + lane * 4] = hv;
}

// ---------------------------------------------------------------------------
// Fused GAT gather, layer2 (H=1, C=64). Half-warp per dst. Output fp32.
// ---------------------------------------------------------------------------
__global__ __launch_bounds__(256) void gat_gather_h1(
    const int* __restrict__ rowptr, const int* __restrict__ csrc,
    const float* __restrict__ w1,
    const float* __restrict__ as_, const float* __restrict__ ad_,
    const __half* __restrict__ hfeat, const float* __restrict__ bias,
    float* __restrict__ outp, int Nn)
{
    int dst = blockIdx.x * 16 + (threadIdx.x >> 4);
    int l   = threadIdx.x & 15;
    if (dst >= Nn) return;

    int beg = rowptr[dst], end = rowptr[dst + 1];
    float4 acc = make_float4(0.f, 0.f, 0.f, 0.f);
    float den = 0.f;
    {
        float ex = __expf(lrelu(as_[dst] + ad_[dst]));
        den += ex;
        const uint2* hp = (const uint2*)(hfeat + (size_t)dst * C2);
        uint2 raw = hp[l];
        float2 f0 = __half22float2(*(__half2*)&raw.x);
        float2 f1 = __half22float2(*(__half2*)&raw.y);
        acc.x += ex * f0.x; acc.y += ex * f0.y; acc.z += ex * f1.x; acc.w += ex * f1.y;
    }
    #pragma unroll 8
    for (int j = beg; j < end; ++j) {
        int s = csrc[j];
        float ex = w1[j];
        den += ex;
        const uint2* hp = (const uint2*)(hfeat + (size_t)s * C2);
        uint2 raw = hp[l];
        float2 f0 = __half22float2(*(__half2*)&raw.x);
        float2 f1 = __half22float2(*(__half2*)&raw.y);
        acc.x += ex * f0.x; acc.y += ex * f0.y; acc.z += ex * f1.x; acc.w += ex * f1.y;
    }
    float r = 1.f / den;
    float4 b = *(const float4*)&bias[l * 4];
    float4 o = make_float4(acc.x * r + b.x, acc.y * r + b.y,
                           acc.z * r + b.z, acc.w * r + b.w);
    *(float4*)&outp[(size_t)dst * C2 + l * 4] = o;
}

// ---------------------------------------------------------------------------
// Launch: CSR build on a side stream, overlapped with convert + layer1 GEMM.
// ---------------------------------------------------------------------------
extern "C" void kernel_launch(void* const* d_in, const int* in_sizes, int n_in,
                              void* d_out, int out_size)
{
    const float* x    = (const float*)d_in[0];
    const int*   ei   = (const int*)  d_in[1];
    const float* W1   = (const float*)d_in[2];
    const float* aS1  = (const float*)d_in[3];
    const float* aD1  = (const float*)d_in[4];
    const float* b1   = (const float*)d_in[5];
    const float* W2   = (const float*)d_in[6];
    const float* aS2  = (const float*)d_in[7];
    const float* aD2  = (const float*)d_in[8];
    const float* b2   = (const float*)d_in[9];
    float* out = (float*)d_out;

    const int N = in_sizes[0] / 128;   // 50000
    const int E = in_sizes[1] / 2;     // 800000
    const int NB = (N + SCAN_BLK - 1) / SCAN_BLK;

    __half *xh, *w1h, *w2h, *h1, *agg1h, *h2;
    float *as1, *ad1, *as2, *ad2, *w4, *w1;
    int *deg, *rowptr, *cursor, *csrc, *bsum, *bofs;
    cudaGetSymbolAddress((void**)&xh,     g_xh);
    cudaGetSymbolAddress((void**)&w1h,    g_w1h);
    cudaGetSymbolAddress((void**)&w2h,    g_w2h);
    cudaGetSymbolAddress((void**)&h1,     g_h1);
    cudaGetSymbolAddress((void**)&as1,    g_as1);
    cudaGetSymbolAddress((void**)&ad1,    g_ad1);
    cudaGetSymbolAddress((void**)&agg1h,  g_agg1h);
    cudaGetSymbolAddress((void**)&h2,     g_h2);
    cudaGetSymbolAddress((void**)&as2,    g_as2);
    cudaGetSymbolAddress((void**)&ad2,    g_ad2);
    cudaGetSymbolAddress((void**)&w4,     g_w4);
    cudaGetSymbolAddress((void**)&w1,     g_w1);
    cudaGetSymbolAddress((void**)&deg,    g_deg);
    cudaGetSymbolAddress((void**)&rowptr, g_rowptr);
    cudaGetSymbolAddress((void**)&cursor, g_cursor);
    cudaGetSymbolAddress((void**)&csrc,   g_csrc);
    cudaGetSymbolAddress((void**)&bsum,   g_bsum);
    cudaGetSymbolAddress((void**)&bofs,   g_bofs);

    static cudaStream_t side = nullptr;
    static cudaEvent_t evf = nullptr, evj = nullptr;
    if (side == nullptr) {
        cudaStreamCreateWithFlags(&side, cudaStreamNonBlocking);
        cudaEventCreateWithFlags(&evf, cudaEventDisableTiming);
        cudaEventCreateWithFlags(&evj, cudaEventDisableTiming);
    }

    const int warpBlocks = (N + 7) / 8;

    // -------- fork: CSR build on side stream --------
    cudaEventRecord(evf, 0);
    cudaStreamWaitEvent(side, evf, 0);
    cudaMemsetAsync(deg, 0, (size_t)N * sizeof(int), side);
    hist_kernel<<<(E + 255) / 256, 256, 0, side>>>(ei, deg, E);
    block_sum_kernel<<<NB, 256, 0, side>>>(deg, bsum, N);
    scan_bsums_kernel<<<1, 64, 0, side>>>(bsum, bofs, rowptr, N, NB);
    write_rowptr_kernel<<<NB, 256, 0, side>>>(deg, bofs, rowptr, cursor, N);
    scatter_kernel<<<(E + 255) / 256, 256, 0, side>>>(ei, cursor, csrc, E);
    cudaEventRecord(evj, side);

    // -------- main stream: convert inputs to fp16, then tensor GEMM1 --------
    {
        long n4 = (long)N * 128 / 4;
        f2h_kernel<<<(int)((n4 + 255) / 256), 256>>>(x, xh, n4);
        long w1n = 128 * F1 / 4;
        f2h_kernel<<<(int)((w1n + 255) / 256), 256>>>(W1, w1h, w1n);
        long w2n = F1 * C2 / 4;
        f2h_kernel<<<(int)((w2n + 255) / 256), 256>>>(W2, w2h, w2n);
    }
    {
        dim3 grid(F1 / 64, (N + 127) / 128);
        hgemm_att_kernel<<<grid, 256>>>(xh, w1h, h1, aS1, aD1, as1, ad1, N, F1, 128);
    }

    // -------- join, then the dependent pipeline --------
    cudaStreamWaitEvent(0, evj, 0);
    edge_w4_kernel<<<warpBlocks, 256>>>(rowptr, csrc, as1, ad1, w4, N);
    gat_gather_h4<<<(2 * N + 7) / 8, 256>>>(rowptr, csrc, w4, as1, ad1, h1, b1, agg1h, N);
    {
        dim3 grid(C2 / 64, (N + 127) / 128);
        hgemm_att_kernel<<<grid, 256>>>(agg1h, w2h, h2, aS2, aD2, as2, ad2, N, C2, F1);
    }
    edge_w1_kernel<<<warpBlocks, 256>>>(rowptr, csrc, as2, ad2, w1, N);
    gat_gather_h1<<<(N + 15) / 16, 256>>>(rowptr, csrc, w1, as2, ad2, h2, b2, out, N);
}

// round 16
// speedup vs baseline: 1.5094x; 1.0071x over previous
#include <cuda_runtime.h>
#include <cuda_fp16.h>
#include <cstdint>

// ---------------------------------------------------------------------------
// Problem constants (shapes fixed by the dataset)
// ---------------------------------------------------------------------------
#define NMAX 50000
#define EMAX 800000
#define H1 4
#define C1 64
#define F1 (H1 * C1)   // 256
#define C2 64
#define SCAN_BLK 1024
#define NBMAX 64

// ---------------------------------------------------------------------------
// Scratch (static device memory; no allocation anywhere)
// ---------------------------------------------------------------------------
__device__ __half g_xh[(size_t)NMAX * 128];    // x fp16
__device__ __half g_w1h[128 * F1];             // W1 fp16
__device__ __half g_w2h[F1 * C2];              // W2 fp16
__device__ __half g_h1[(size_t)NMAX * F1];     // layer1 features fp16
__device__ float  g_as1[NMAX * H1];
__device__ float  g_ad1[NMAX * H1];
__device__ __half g_agg1h[(size_t)NMAX * F1];  // layer1 output fp16 (feeds hgemm2)
__device__ __half g_h2[(size_t)NMAX * C2];     // layer2 features fp16
__device__ float  g_as2[NMAX];
__device__ float  g_ad2[NMAX];
__device__ float  g_w4[(size_t)EMAX * H1];     // layer1 per-edge softmax weights
__device__ float  g_w1[EMAX];                  // layer2 per-edge softmax weights
__device__ int g_deg[NMAX];
__device__ int g_rowptr[NMAX + 1];
__device__ int g_cursor[NMAX];
__device__ int g_csrc[EMAX];
__device__ int g_bsum[NBMAX];
__device__ int g_bofs[NBMAX];

__device__ __forceinline__ float lrelu(float v) { return v > 0.f ? v : 0.2f * v; }

struct half4 { __half2 a, b; };

// ---------------------------------------------------------------------------
// fp32 -> fp16 elementwise conversion (vectorized), n multiple of 4
// ---------------------------------------------------------------------------
__global__ __launch_bounds__(256) void f2h_kernel(
    const float* __restrict__ in, __half* __restrict__ out, long n4)
{
    long t = (long)blockIdx.x * blockDim.x + threadIdx.x;
    if (t >= n4) return;
    float4 v = ((const float4*)in)[t];
    half4 h;
    h.a = __floats2half2_rn(v.x, v.y);
    h.b = __floats2half2_rn(v.z, v.w);
    ((half4*)out)[t] = h;
}

// ---------------------------------------------------------------------------
// fp16 tensor-core GEMM (mma.sync.m16n8k16) with fused attention epilogue.
// C[M,N] = A[M,K]*B[K,N], A/B fp16 row-major, C fp16, att scalars fp32.
// Block 128x64, BK=32, 256 thr = 8 warps (4 M x 2 N), warp tile 32x32.
// ---------------------------------------------------------------------------
__global__ __launch_bounds__(256) void hgemm_att_kernel(
    const __half* __restrict__ A, const __half* __restrict__ B,
    __half* __restrict__ C, const float* __restrict__ att_s,
    const float* __restrict__ att_d, float* __restrict__ as_out,
    float* __restrict__ ad_out, int M, int N, int K)
{
    const int BM = 128, BK = 32, SAS = 40;
    __shared__ __half As[BM][SAS];
    __shared__ __half Bs[64][SAS];
    __shared__ float red[BM][4];

    int tid = threadIdx.x;
    int wid = tid >> 5, lane = tid & 31;
    int wm = (wid & 3) * 32;
    int wn = (wid >> 2) * 32;
    int g  = lane >> 2;
    int tg = lane & 3;
    int bm = blockIdx.y * BM;
    int bn = blockIdx.x * 64;

    float acc[2][4][4] = {};

    for (int k0 = 0; k0 < K; k0 += BK) {
        #pragma unroll
        for (int i = 0; i < 2; ++i) {
            int idx = tid + i * 256;
            int r  = idx >> 2;
            int c8 = idx & 3;
            int gr = bm + r;
            uint4 v = make_uint4(0u, 0u, 0u, 0u);
            if (gr < M) v = *(const uint4*)&A[(size_t)gr * K + k0 + c8 * 8];
            *(uint4*)&As[r][c8 * 8] = v;
        }
        {
            int kr = tid >> 3;
            int cb = tid & 7;
            uint4 v = *(const uint4*)&B[(size_t)(k0 + kr) * N + bn + cb * 8];
            __half h[8];
            *(uint4*)h = v;
            #pragma unroll
            for (int j = 0; j < 8; ++j) Bs[cb * 8 + j][kr] = h[j];
        }
        __syncthreads();

        #pragma unroll
        for (int ks = 0; ks < 2; ++ks) {
            int kb = ks * 16;
            unsigned a[2][4], b[4][2];
            #pragma unroll
            for (int mm = 0; mm < 2; ++mm) {
                int r0 = wm + mm * 16 + g;
                a[mm][0] = *(const unsigned*)&As[r0][kb + tg * 2];
                a[mm][1] = *(const unsigned*)&As[r0 + 8][kb + tg * 2];
                a[mm][2] = *(const unsigned*)&As[r0][kb + tg * 2 + 8];
                a[mm][3] = *(const unsigned*)&As[r0 + 8][kb + tg * 2 + 8];
            }
            #pragma unroll
            for (int nn = 0; nn < 4; ++nn) {
                int c0 = wn + nn * 8 + g;
                b[nn][0] = *(const unsigned*)&Bs[c0][kb + tg * 2];
                b[nn][1] = *(const unsigned*)&Bs[c0][kb + tg * 2 + 8];
            }
            #pragma unroll
            for (int mm = 0; mm < 2; ++mm)
                #pragma unroll
                for (int nn = 0; nn < 4; ++nn) {
                    asm("mma.sync.aligned.m16n8k16.row.col.f32.f16.f16.f32 "
                        "{%0,%1,%2,%3},{%4,%5,%6,%7},{%8,%9},{%0,%1,%2,%3};"
                        : "+f"(acc[mm][nn][0]), "+f"(acc[mm][nn][1]),
                          "+f"(acc[mm][nn][2]), "+f"(acc[mm][nn][3])
                        : "r"(a[mm][0]), "r"(a[mm][1]), "r"(a[mm][2]), "r"(a[mm][3]),
                          "r"(b[nn][0]), "r"(b[nn][1]));
                }
        }
        __syncthreads();
    }

    #pragma unroll
    for (int mm = 0; mm < 2; ++mm) {
        int r0 = bm + wm + mm * 16 + g;
        #pragma unroll
        for (int nn = 0; nn < 4; ++nn) {
            int c = bn + wn + nn * 8 + tg * 2;
            if (r0 < M)
                *(__half2*)&C[(size_t)r0 * N + c] =
                    __floats2half2_rn(acc[mm][nn][0], acc[mm][nn][1]);
            if (r0 + 8 < M)
                *(__half2*)&C[(size_t)(r0 + 8) * N + c] =
                    __floats2half2_rn(acc[mm][nn][2], acc[mm][nn][3]);
        }
    }

    int hh = blockIdx.x;
    int Hh = N >> 6;
    float2 avs[4], avd[4];
    #pragma unroll
    for (int nn = 0; nn < 4; ++nn) {
        int c = hh * 64 + wn + nn * 8 + tg * 2;
        avs[nn] = *(const float2*)&att_s[c];
        avd[nn] = *(const float2*)&att_d[c];
    }
    #pragma unroll
    for (int mm = 0; mm < 2; ++mm) {
        #pragma unroll
        for (int h = 0; h < 2; ++h) {
            float sa = 0.f, sd = 0.f;
            #pragma unroll
            for (int nn = 0; nn < 4; ++nn) {
                sa += acc[mm][nn][2 * h] * avs[nn].x + acc[mm][nn][2 * h + 1] * avs[nn].y;
                sd += acc[mm][nn][2 * h] * avd[nn].x + acc[mm][nn][2 * h + 1] * avd[nn].y;
            }
            #pragma unroll
            for (int o = 1; o < 4; o <<= 1) {
                sa += __shfl_xor_sync(0xffffffffu, sa, o);
                sd += __shfl_xor_sync(0xffffffffu, sd, o);
            }
            if (tg == 0) {
                int lr = wm + mm * 16 + h * 8 + g;
                red[lr][(wn >> 5) * 2 + 0] = sa;
                red[lr][(wn >> 5) * 2 + 1] = sd;
            }
        }
    }
    __syncthreads();
    if (tid < BM) {
        int gr = bm + tid;
        if (gr < M) {
            as_out[gr * Hh + hh] = red[tid][0] + red[tid][2];
            ad_out[gr * Hh + hh] = red[tid][1] + red[tid][3];
        }
    }
}

// ---------------------------------------------------------------------------
// CSR build: histogram, 3-phase parallel scan, scatter.
// ---------------------------------------------------------------------------
__global__ __launch_bounds__(256) void hist_kernel(
    const int* __restrict__ ei, int* __restrict__ deg, int E)
{
    int t = blockIdx.x * blockDim.x + threadIdx.x;
    if (t < E) atomicAdd(&deg[ei[E + t]], 1);
}

__global__ __launch_bounds__(256) void block_sum_kernel(
    const int* __restrict__ deg, int* __restrict__ bsum, int Nn)
{
    __shared__ int ss[256];
    int tid = threadIdx.x;
    int base = blockIdx.x * SCAN_BLK + tid * 4;
    int s = 0;
    #pragma unroll
    for (int i = 0; i < 4; ++i) {
        int idx = base + i;
        if (idx < Nn) s += deg[idx];
    }
    ss[tid] = s;
    __syncthreads();
    #pragma unroll
    for (int o = 128; o; o >>= 1) {
        if (tid < o) ss[tid] += ss[tid + o];
        __syncthreads();
    }
    if (tid == 0) bsum[blockIdx.x] = ss[0];
}

__global__ __launch_bounds__(64) void scan_bsums_kernel(
    const int* __restrict__ bsum, int* __restrict__ bofs,
    int* __restrict__ rowptr, int Nn, int NB)
{
    __shared__ int ss[64];
    int tid = threadIdx.x;
    int v = (tid < NB) ? bsum[tid] : 0;
    ss[tid] = v;
    __syncthreads();
    #pragma unroll
    for (int o = 1; o < 64; o <<= 1) {
        int u = (tid >= o) ? ss[tid - o] : 0;
        __syncthreads();
        ss[tid] += u;
        __syncthreads();
    }
    if (tid < NB) bofs[tid] = ss[tid] - v;
    if (tid == NB - 1) rowptr[Nn] = ss[tid];
}

__global__ __launch_bounds__(256) void write_rowptr_kernel(
    const int* __restrict__ deg, const int* __restrict__ bofs,
    int* __restrict__ rowptr, int* __restrict__ cursor, int Nn)
{
    __shared__ int ss[256];
    int tid = threadIdx.x;
    int base = blockIdx.x * SCAN_BLK + tid * 4;
    int loc[4];
    int tsum = 0;
    #pragma unroll
    for (int i = 0; i < 4; ++i) {
        int idx = base + i;
        loc[i] = (idx < Nn) ? deg[idx] : 0;
        tsum += loc[i];
    }
    ss[tid] = tsum;
    __syncthreads();
    #pragma unroll
    for (int o = 1; o < 256; o <<= 1) {
        int u = (tid >= o) ? ss[tid - o] : 0;
        __syncthreads();
        ss[tid] += u;
        __syncthreads();
    }
    int run = (tid ? ss[tid - 1] : 0) + bofs[blockIdx.x];
    #pragma unroll
    for (int i = 0; i < 4; ++i) {
        int idx = base + i;
        if (idx < Nn) {
            rowptr[idx] = run;
            cursor[idx] = run;
            run += loc[i];
        }
    }
}

__global__ __launch_bounds__(256) void scatter_kernel(
    const int* __restrict__ ei, int* __restrict__ cursor,
    int* __restrict__ csrc, int E)
{
    int t = blockIdx.x * blockDim.x + threadIdx.x;
    if (t < E) {
        int d = ei[E + t];
        int p = atomicAdd(&cursor[d], 1);
        csrc[p] = ei[t];
    }
}

// ---------------------------------------------------------------------------
// Per-edge softmax weights (lane-parallel over edges; latency hidden).
// ---------------------------------------------------------------------------
__global__ __launch_bounds__(256) void edge_w4_kernel(
    const int* __restrict__ rowptr, const int* __restrict__ csrc,
    const float* __restrict__ as_, const float* __restrict__ ad_,
    float* __restrict__ w4, int Nn)
{
    int dst  = (blockIdx.x * blockDim.x + threadIdx.x) >> 5;
    int lane = threadIdx.x & 31;
    if (dst >= Nn) return;
    int beg = rowptr[dst], end = rowptr[dst + 1];
    float4 ad4 = *(const float4*)&ad_[dst * 4];
    for (int j = beg + lane; j < end; j += 32) {
        int s = csrc[j];
        float4 a = *(const float4*)&as_[s * 4];
        float4 w;
        w.x = __expf(lrelu(a.x + ad4.x));
        w.y = __expf(lrelu(a.y + ad4.y));
        w.z = __expf(lrelu(a.z + ad4.z));
        w.w = __expf(lrelu(a.w + ad4.w));
        *(float4*)&w4[(size_t)j * 4] = w;
    }
}

__global__ __launch_bounds__(256) void edge_w1_kernel(
    const int* __restrict__ rowptr, const int* __restrict__ csrc,
    const float* __restrict__ as_, const float* __restrict__ ad_,
    float* __restrict__ w1, int Nn)
{
    int dst  = (blockIdx.x * blockDim.x + threadIdx.x) >> 5;
    int lane = threadIdx.x & 31;
    if (dst >= Nn) return;
    int beg = rowptr[dst], end = rowptr[dst + 1];
    float ad = ad_[dst];
    for (int j = beg + lane; j < end; j += 32) {
        int s = csrc[j];
        w1[j] = __expf(lrelu(as_[s] + ad));
    }
}

// ---------------------------------------------------------------------------
// Fused GAT gather, layer1 (H=4, C=64). ONE warp per dst covering ALL 4
// heads: lane l owns channels 8l..8l+7 (uint4 = 16B fp16), head = l>>3.
// Per edge: 1 uniform csrc + 1 uniform float4 w4 + one 512B feature row.
// Per-lane denominator = its own head's -> NO shuffles. Bias+ELU fused.
// Output fp16 (feeds tensor GEMM2).
// ---------------------------------------------------------------------------
__global__ __launch_bounds__(256) void gat_gather_h4(
    const int* __restrict__ rowptr, const int* __restrict__ csrc,
    const float* __restrict__ w4,
    const float* __restrict__ as_, const float* __restrict__ ad_,
    const __half* __restrict__ hfeat, const float* __restrict__ bias,
    __half* __restrict__ outp, int Nn)
{
    int dst  = blockIdx.x * 8 + (threadIdx.x >> 5);
    int lane = threadIdx.x & 31;
    if (dst >= Nn) return;

    int beg = rowptr[dst], end = rowptr[dst + 1];
    int head = lane >> 3;

    float acc[8] = {};
    float den = 0.f;

    // self-loop (weights inline, O(1))
    {
        float4 ad4 = *(const float4*)&ad_[dst * 4];
        float4 as4 = *(const float4*)&as_[dst * 4];
        float e0 = __expf(lrelu(as4.x + ad4.x));
        float e1 = __expf(lrelu(as4.y + ad4.y));
        float e2 = __expf(lrelu(as4.z + ad4.z));
        float e3 = __expf(lrelu(as4.w + ad4.w));
        float ex = head == 0 ? e0 : head == 1 ? e1 : head == 2 ? e2 : e3;
        den += ex;
        uint4 raw = *(const uint4*)(hfeat + (size_t)dst * F1 + lane * 8);
        float2 a0 = __half22float2(*(__half2*)&raw.x);
        float2 a1 = __half22float2(*(__half2*)&raw.y);
        float2 a2 = __half22float2(*(__half2*)&raw.z);
        float2 a3 = __half22float2(*(__half2*)&raw.w);
        acc[0] += ex * a0.x; acc[1] += ex * a0.y;
        acc[2] += ex * a1.x; acc[3] += ex * a1.y;
        acc[4] += ex * a2.x; acc[5] += ex * a2.y;
        acc[6] += ex * a3.x; acc[7] += ex * a3.y;
    }
    #pragma unroll 4
    for (int j = beg; j < end; ++j) {
        int s = csrc[j];                               // uniform
        float4 w = *(const float4*)&w4[(size_t)j * 4]; // uniform
        float ex = head == 0 ? w.x : head == 1 ? w.y : head == 2 ? w.z : w.w;
        den += ex;
        uint4 raw = *(const uint4*)(hfeat + (size_t)s * F1 + lane * 8);
        float2 a0 = __half22float2(*(__half2*)&raw.x);
        float2 a1 = __half22float2(*(__half2*)&raw.y);
        float2 a2 = __half22float2(*(__half2*)&raw.z);
        float2 a3 = __half22float2(*(__half2*)&raw.w);
        acc[0] += ex * a0.x; acc[1] += ex * a0.y;
        acc[2] += ex * a1.x; acc[3] += ex * a1.y;
        acc[4] += ex * a2.x; acc[5] += ex * a2.y;
        acc[6] += ex * a3.x; acc[7] += ex * a3.y;
    }

    float r = 1.f / den;
    const float* bp = &bias[lane * 8];
    float o[8];
    #pragma unroll
    for (int i = 0; i < 8; ++i) {
        float v = acc[i] * r + bp[i];
        o[i] = v > 0.f ? v : expm1f(v);
    }
    __half2 h0 = __floats2half2_rn(o[0], o[1]);
    __half2 h1v = __floats2half2_rn(o[2], o[3]);
    __half2 h2v = __floats2half2_rn(o[4], o[5]);
    __half2 h3 = __floats2half2_rn(o[6], o[7]);
    uint4 packed;
    packed.x = *(unsigned*)&h0;
    packed.y = *(unsigned*)&h1v;
    packed.z = *(unsigned*)&h2v;
    packed.w = *(unsigned*)&h3;
    *(uint4*)(outp + (size_t)dst * F1 + lane * 8) = packed;
}

// ---------------------------------------------------------------------------
// Fused GAT gather, layer2 (H=1, C=64). Half-warp per dst. Output fp32.
// ---------------------------------------------------------------------------
__global__ __launch_bounds__(256) void gat_gather_h1(
    const int* __restrict__ rowptr, const int* __restrict__ csrc,
    const float* __restrict__ w1,
    const float* __restrict__ as_, const float* __restrict__ ad_,
    const __half* __restrict__ hfeat, const float* __restrict__ bias,
    float* __restrict__ outp, int Nn)
{
    int dst = blockIdx.x * 16 + (threadIdx.x >> 4);
    int l   = threadIdx.x & 15;
    if (dst >= Nn) return;

    int beg = rowptr[dst], end = rowptr[dst + 1];
    float4 acc = make_float4(0.f, 0.f, 0.f, 0.f);
    float den = 0.f;
    {
        float ex = __expf(lrelu(as_[dst] + ad_[dst]));
        den += ex;
        const uint2* hp = (const uint2*)(hfeat + (size_t)dst * C2);
        uint2 raw = hp[l];
        float2 f0 = __half22float2(*(__half2*)&raw.x);
        float2 f1 = __half22float2(*(__half2*)&raw.y);
        acc.x += ex * f0.x; acc.y += ex * f0.y; acc.z += ex * f1.x; acc.w += ex * f1.y;
    }
    #pragma unroll 8
    for (int j = beg; j < end; ++j) {
        int s = csrc[j];
        float ex = w1[j];
        den += ex;
        const uint2* hp = (const uint2*)(hfeat + (size_t)s * C2);
        uint2 raw = hp[l];
        float2 f0 = __half22float2(*(__half2*)&raw.x);
        float2 f1 = __half22float2(*(__half2*)&raw.y);
        acc.x += ex * f0.x; acc.y += ex * f0.y; acc.z += ex * f1.x; acc.w += ex * f1.y;
    }
    float r = 1.f / den;
    float4 b = *(const float4*)&bias[l * 4];
    float4 o = make_float4(acc.x * r + b.x, acc.y * r + b.y,
                           acc.z * r + b.z, acc.w * r + b.w);
    *(float4*)&outp[(size_t)dst * C2 + l * 4] = o;
}

// ---------------------------------------------------------------------------
// Launch: CSR build on a side stream, overlapped with convert + layer1 GEMM.
// ---------------------------------------------------------------------------
extern "C" void kernel_launch(void* const* d_in, const int* in_sizes, int n_in,
                              void* d_out, int out_size)
{
    const float* x    = (const float*)d_in[0];
    const int*   ei   = (const int*)  d_in[1];
    const float* W1   = (const float*)d_in[2];
    const float* aS1  = (const float*)d_in[3];
    const float* aD1  = (const float*)d_in[4];
    const float* b1   = (const float*)d_in[5];
    const float* W2   = (const float*)d_in[6];
    const float* aS2  = (const float*)d_in[7];
    const float* aD2  = (const float*)d_in[8];
    const float* b2   = (const float*)d_in[9];
    float* out = (float*)d_out;

    const int N = in_sizes[0] / 128;   // 50000
    const int E = in_sizes[1] / 2;     // 800000
    const int NB = (N + SCAN_BLK - 1) / SCAN_BLK;

    __half *xh, *w1h, *w2h, *h1, *agg1h, *h2;
    float *as1, *ad1, *as2, *ad2, *w4, *w1;
    int *deg, *rowptr, *cursor, *csrc, *bsum, *bofs;
    cudaGetSymbolAddress((void**)&xh,     g_xh);
    cudaGetSymbolAddress((void**)&w1h,    g_w1h);
    cudaGetSymbolAddress((void**)&w2h,    g_w2h);
    cudaGetSymbolAddress((void**)&h1,     g_h1);
    cudaGetSymbolAddress((void**)&as1,    g_as1);
    cudaGetSymbolAddress((void**)&ad1,    g_ad1);
    cudaGetSymbolAddress((void**)&agg1h,  g_agg1h);
    cudaGetSymbolAddress((void**)&h2,     g_h2);
    cudaGetSymbolAddress((void**)&as2,    g_as2);
    cudaGetSymbolAddress((void**)&ad2,    g_ad2);
    cudaGetSymbolAddress((void**)&w4,     g_w4);
    cudaGetSymbolAddress((void**)&w1,     g_w1);
    cudaGetSymbolAddress((void**)&deg,    g_deg);
    cudaGetSymbolAddress((void**)&rowptr, g_rowptr);
    cudaGetSymbolAddress((void**)&cursor, g_cursor);
    cudaGetSymbolAddress((void**)&csrc,   g_csrc);
    cudaGetSymbolAddress((void**)&bsum,   g_bsum);
    cudaGetSymbolAddress((void**)&bofs,   g_bofs);

    static cudaStream_t side = nullptr;
    static cudaEvent_t evf = nullptr, evj = nullptr;
    if (side == nullptr) {
        cudaStreamCreateWithFlags(&side, cudaStreamNonBlocking);
        cudaEventCreateWithFlags(&evf, cudaEventDisableTiming);
        cudaEventCreateWithFlags(&evj, cudaEventDisableTiming);
    }

    const int warpBlocks = (N + 7) / 8;

    // -------- fork: CSR build on side stream --------
    cudaEventRecord(evf, 0);
    cudaStreamWaitEvent(side, evf, 0);
    cudaMemsetAsync(deg, 0, (size_t)N * sizeof(int), side);
    hist_kernel<<<(E + 255) / 256, 256, 0, side>>>(ei, deg, E);
    block_sum_kernel<<<NB, 256, 0, side>>>(deg, bsum, N);
    scan_bsums_kernel<<<1, 64, 0, side>>>(bsum, bofs, rowptr, N, NB);
    write_rowptr_kernel<<<NB, 256, 0, side>>>(deg, bofs, rowptr, cursor, N);
    scatter_kernel<<<(E + 255) / 256, 256, 0, side>>>(ei, cursor, csrc, E);
    cudaEventRecord(evj, side);

    // -------- main stream: convert inputs to fp16, then tensor GEMM1 --------
    {
        long n4 = (long)N * 128 / 4;
        f2h_kernel<<<(int)((n4 + 255) / 256), 256>>>(x, xh, n4);
        long w1n = 128 * F1 / 4;
        f2h_kernel<<<(int)((w1n + 255) / 256), 256>>>(W1, w1h, w1n);
        long w2n = F1 * C2 / 4;
        f2h_kernel<<<(int)((w2n + 255) / 256), 256>>>(W2, w2h, w2n);
    }
    {
        dim3 grid(F1 / 64, (N + 127) / 128);
        hgemm_att_kernel<<<grid, 256>>>(xh, w1h, h1, aS1, aD1, as1, ad1, N, F1, 128);
    }

    // -------- join, then the dependent pipeline --------
    cudaStreamWaitEvent(0, evj, 0);
    edge_w4_kernel<<<warpBlocks, 256>>>(rowptr, csrc, as1, ad1, w4, N);
    gat_gather_h4<<<warpBlocks, 256>>>(rowptr, csrc, w4, as1, ad1, h1, b1, agg1h, N);
    {
        dim3 grid(C2 / 64, (N + 127) / 128);
        hgemm_att_kernel<<<grid, 256>>>(agg1h, w2h, h2, aS2, aD2, as2, ad2, N, C2, F1);
    }
    edge_w1_kernel<<<warpBlocks, 256>>>(rowptr, csrc, as2, ad2, w1, N);
    gat_gather_h1<<<(N + 15) / 16, 256>>>(rowptr, csrc, w1, as2, ad2, h2, b2, out, N);
}